// round 13
// baseline (speedup 1.0000x reference)
#include <cuda_runtime.h>
#include <cuda_bf16.h>
#include <math.h>
#include <stdint.h>

#define BB 16
#define SS 1024
#define DD 1024
#define CH 32
#define RR 512            // CH*BB rows per chunk
#define NC 32             // SS/CH chunks
#define SB (SS*BB)        // 16384 rows total
#define ETA_F (0.01f*2.0f/(16.0f*1024.0f))

// ---------------- device scratch ----------------
__device__ float g_HT[SB*DD];
__device__ float g_STATE[SB*DD];
__device__ float g_PROBE[SB*DD];
__device__ float g_PBASE[SB*DD];
__device__ float g_OT[SB*DD];
__device__ float g_X1[SB*DD];
__device__ float g_H2[SB*DD];
__device__ float g_U[SB*DD];
__device__ __nv_bfloat16 g_HTh[SB*DD];
__device__ __nv_bfloat16 g_TVh[SB*DD];
__device__ __nv_bfloat16 g_TVth[SB*DD];   // per-chunk transposed TV [NC][DD][RR]
__device__ __nv_bfloat16 g_ABh[SB*DD];    // base A = TV@W0^T - STATE (bf16)
__device__ __nv_bfloat16 g_PRh[SB*DD];
__device__ __nv_bfloat16 g_Wsth[DD*DD];
__device__ __nv_bfloat16 g_W0h[DD*DD];
__device__ __nv_bfloat16 g_Hbh[(long)NC*RR*RR];
__device__ __nv_bfloat16 g_INC[(long)NC*DD*DD];  // per-chunk TV^T AB
__device__ __nv_bfloat16 g_St[(long)NC*DD*DD];   // prefix sums

// ---------------- helpers ----------------
__device__ __forceinline__ float tf32r(float x) {
    unsigned u;
    asm("cvt.rna.tf32.f32 %0, %1;" : "=r"(u) : "f"(x));
    return __uint_as_float(u);
}
__device__ __forceinline__ uint32_t smem_u32(const void* p) {
    uint32_t a;
    asm("{ .reg .u64 t; cvta.to.shared.u64 t, %1; cvt.u32.u64 %0, t; }"
        : "=r"(a) : "l"(p));
    return a;
}
__device__ __forceinline__ void cpa16(uint32_t d, const void* g) {
    asm volatile("cp.async.cg.shared.global [%0], [%1], 16;" :: "r"(d), "l"(g));
}
__device__ __forceinline__ void cpa_commit() {
    asm volatile("cp.async.commit_group;" ::: "memory");
}
__device__ __forceinline__ void mma_tf32(float* c, const unsigned* a, const unsigned* b) {
    asm volatile(
        "mma.sync.aligned.m16n8k8.row.col.f32.tf32.tf32.f32 "
        "{%0,%1,%2,%3}, {%4,%5,%6,%7}, {%8,%9}, {%0,%1,%2,%3};\n"
        : "+f"(c[0]), "+f"(c[1]), "+f"(c[2]), "+f"(c[3])
        : "r"(a[0]), "r"(a[1]), "r"(a[2]), "r"(a[3]), "r"(b[0]), "r"(b[1]));
}
__device__ __forceinline__ void mma_bf16(float* c, const unsigned* a, const unsigned* b) {
    asm volatile(
        "mma.sync.aligned.m16n8k16.row.col.f32.bf16.bf16.f32 "
        "{%0,%1,%2,%3}, {%4,%5,%6,%7}, {%8,%9}, {%0,%1,%2,%3};\n"
        : "+f"(c[0]), "+f"(c[1]), "+f"(c[2]), "+f"(c[3])
        : "r"(a[0]), "r"(a[1]), "r"(a[2]), "r"(a[3]), "r"(b[0]), "r"(b[1]));
}
__device__ __forceinline__ void ldsm4(unsigned& r0, unsigned& r1, unsigned& r2,
                                      unsigned& r3, unsigned addr) {
    asm volatile("ldmatrix.sync.aligned.m8n8.x4.shared.b16 {%0,%1,%2,%3},[%4];"
                 : "=r"(r0), "=r"(r1), "=r"(r2), "=r"(r3) : "r"(addr));
}
__device__ __forceinline__ void ldsm4t(unsigned& r0, unsigned& r1, unsigned& r2,
                                       unsigned& r3, unsigned addr) {
    asm volatile("ldmatrix.sync.aligned.m8n8.x4.trans.shared.b16 {%0,%1,%2,%3},[%4];"
                 : "=r"(r0), "=r"(r1), "=r"(r2), "=r"(r3) : "r"(addr));
}

// ---------------- elementwise kernels ----------------
__global__ void k_cvt(const float* __restrict__ a, __nv_bfloat16* __restrict__ ah,
                      const float* __restrict__ b, __nv_bfloat16* __restrict__ bh) {
    long i = (long)blockIdx.x * blockDim.x + threadIdx.x;
    float4 v = *(const float4*)(a + i*4);
    *(__nv_bfloat162*)(ah + i*4)     = __floats2bfloat162_rn(v.x, v.y);
    *(__nv_bfloat162*)(ah + i*4 + 2) = __floats2bfloat162_rn(v.z, v.w);
    float4 w = *(const float4*)(b + i*4);
    *(__nv_bfloat162*)(bh + i*4)     = __floats2bfloat162_rn(w.x, w.y);
    *(__nv_bfloat162*)(bh + i*4 + 2) = __floats2bfloat162_rn(w.z, w.w);
}

__global__ void k_prep(const float* __restrict__ x, const float* __restrict__ a1,
                       float* __restrict__ HT, __nv_bfloat16* __restrict__ HTh) {
    long i4 = (long)blockIdx.x * blockDim.x + threadIdx.x;
    long flat = i4 * 4;
    int b = (int)(flat / ((long)SS*DD));
    int t = (int)((flat / DD) % SS);
    int d = (int)(flat % DD);
    float4 xv = *(const float4*)(x + flat);
    float4 av = *(const float4*)(a1 + d);
    float4 o;
    o.x = tanhf(av.x * xv.x); o.y = tanhf(av.y * xv.y);
    o.z = tanhf(av.z * xv.z); o.w = tanhf(av.w * xv.w);
    const long di = (long)(t*BB + b) * DD + d;
    *(float4*)(HT + di) = o;
    *(__nv_bfloat162*)(HTh + di)     = __floats2bfloat162_rn(o.x, o.y);
    *(__nv_bfloat162*)(HTh + di + 2) = __floats2bfloat162_rn(o.z, o.w);
}

__global__ void k_tv(const float* __restrict__ ST, const float* __restrict__ noise,
                     __nv_bfloat16* __restrict__ TVh) {
    long i4 = (long)blockIdx.x * blockDim.x + threadIdx.x;
    long flat = i4 * 4;
    int t = (int)(flat / ((long)BB*DD));
    int b = (int)((flat / DD) % BB);
    int d = (int)(flat % DD);
    float4 s = *(const float4*)(ST + flat);
    float4 n = *(const float4*)(noise + ((long)b*SS + t) * DD + d);
    *(__nv_bfloat162*)(TVh + flat)     = __floats2bfloat162_rn(s.x+n.x, s.y+n.y);
    *(__nv_bfloat162*)(TVh + flat + 2) = __floats2bfloat162_rn(s.z+n.z, s.w+n.w);
}

// batched per-chunk transpose: out[c][d][r] = in[c*RR + r][d]
__global__ void k_trb(const __nv_bfloat16* __restrict__ in,
                      __nv_bfloat16* __restrict__ out) {
    __shared__ __nv_bfloat16 t[32][33];
    const int c = blockIdx.z;
    const int d0 = blockIdx.x * 32, r0 = blockIdx.y * 32;
    const int x = threadIdx.x, y = threadIdx.y;
    const __nv_bfloat16* ip = in + (long)c*RR*DD;
    __nv_bfloat16* op = out + (long)c*DD*RR;
    #pragma unroll
    for (int i = 0; i < 32; i += 8)
        t[y+i][x] = ip[(long)(r0 + y + i) * DD + d0 + x];
    __syncthreads();
    #pragma unroll
    for (int i = 0; i < 32; i += 8)
        op[(long)(d0 + y + i) * RR + r0 + x] = t[x][y+i];
}

// prefix scan over chunks: St[c] = sum_{j<=c} INC[j]   (fp32 accum)
__global__ void k_scan(const __nv_bfloat16* __restrict__ INC,
                       __nv_bfloat16* __restrict__ St) {
    const long idx = (long)blockIdx.x * blockDim.x + threadIdx.x;  // bf162 units
    const long stride = (long)DD*DD/2;
    const __nv_bfloat162* ip = (const __nv_bfloat162*)INC + idx;
    __nv_bfloat162* op = (__nv_bfloat162*)St + idx;
    float sx = 0.f, sy = 0.f;
    for (int c = 0; c < NC; ++c) {
        float2 v = __bfloat1622float2(ip[(long)c*stride]);
        sx += v.x; sy += v.y;
        op[(long)c*stride] = __floats2bfloat162_rn(sx, sy);
    }
}

__global__ void k_x1h2(const float* __restrict__ OT, const float* __restrict__ x,
                       const float* __restrict__ a2,
                       float* __restrict__ X1, float* __restrict__ H2) {
    long i4 = (long)blockIdx.x * blockDim.x + threadIdx.x;
    long flat = i4 * 4;
    int b = (int)(flat / ((long)SS*DD));
    int t = (int)((flat / DD) % SS);
    int d = (int)(flat % DD);
    float4 ro = *(const float4*)(OT + ((long)(t*BB + b) * DD + d));
    float4 xv = *(const float4*)(x + flat);
    float4 av = *(const float4*)(a2 + d);
    float4 x1; x1.x = ro.x+xv.x; x1.y = ro.y+xv.y; x1.z = ro.z+xv.z; x1.w = ro.w+xv.w;
    *(float4*)(X1 + flat) = x1;
    float4 h; h.x = tanhf(av.x*x1.x); h.y = tanhf(av.y*x1.y);
    h.z = tanhf(av.z*x1.z); h.w = tanhf(av.w*x1.w);
    *(float4*)(H2 + flat) = h;
}

// ---------------- tf32 tensor-core GEMM (direct-precision paths) ----------
// MODE: 0 plain  5 gelu  6 C=P1*acc+P2  7 plain + bf16 copy->P2
template<int BM,int BN,int MW,int NW,int MODE>
__global__ void __launch_bounds__(MW*NW*32, 2)
gemm_t(const float* __restrict__ A, int lda,
       const float* __restrict__ B, int ldb,
       float* __restrict__ C, int ldc, int K,
       const float* __restrict__ P1, const float* __restrict__ P2)
{
    constexpr int BK  = 16;
    constexpr int BKp = 20;
    constexpr int T   = MW*NW*32;
    constexpr int WM  = BM/MW, WN = BN/NW;
    constexpr int MT  = WM/16, NT = WN/8;
    constexpr int LPA = BM*BK/(4*T);
    constexpr int LPB = BN*BK/(4*T);

    const int m0 = blockIdx.y * BM, n0 = blockIdx.x * BN;

    __shared__ __align__(16) float As[2][BM][BKp];
    __shared__ __align__(16) float Bs[2][BN][BKp];

    const int tid  = threadIdx.x;
    const int lane = tid & 31;
    const int wid  = tid >> 5;
    const int wm   = wid / NW, wn = wid % NW;
    const int mw0  = wm * WM, nw0 = wn * WN;
    const int qr   = lane >> 2;
    const int qc   = lane & 3;
    const int lr   = lane & 7;
    const int aBase = (mw0 + lr + ((lane>>3)&1)*8) * BKp + ((lane>>4)&1)*4;
    const int bBase = (nw0 + lr + ((lane>>4)&1)*8) * BKp + ((lane>>3)&1)*4;

    float acc[MT][NT][4];
    #pragma unroll
    for (int i = 0; i < MT; ++i)
        #pragma unroll
        for (int j = 0; j < NT; ++j)
            #pragma unroll
            for (int q = 0; q < 4; ++q) acc[i][j][q] = 0.f;

    const int ktiles = K / BK;
    float4 pa[LPA], pb[LPB];

    auto gload = [&](int k0) {
        #pragma unroll
        for (int p = 0; p < LPA; ++p) {
            const int idx = tid + p*T;
            const int am = idx / (BK/4), akq = idx % (BK/4);
            pa[p] = *(const float4*)(A + (long)(m0 + am) * lda + k0 + 4*akq);
        }
        #pragma unroll
        for (int p = 0; p < LPB; ++p) {
            const int idx = tid + p*T;
            const int bn = idx / (BK/4), bkq = idx % (BK/4);
            pb[p] = *(const float4*)(B + (long)(n0 + bn) * ldb + k0 + 4*bkq);
        }
    };
    auto sstore = [&](int s) {
        #pragma unroll
        for (int p = 0; p < LPA; ++p) {
            const int idx = tid + p*T;
            const int am = idx / (BK/4), akq = idx % (BK/4);
            float4 w = make_float4(tf32r(pa[p].x), tf32r(pa[p].y),
                                   tf32r(pa[p].z), tf32r(pa[p].w));
            *(float4*)&As[s][am][4*akq] = w;
        }
        #pragma unroll
        for (int p = 0; p < LPB; ++p) {
            const int idx = tid + p*T;
            const int bn = idx / (BK/4), bkq = idx % (BK/4);
            float4 w = make_float4(tf32r(pb[p].x), tf32r(pb[p].y),
                                   tf32r(pb[p].z), tf32r(pb[p].w));
            *(float4*)&Bs[s][bn][4*bkq] = w;
        }
    };
    auto compute = [&](int s) {
        const unsigned sA = (unsigned)__cvta_generic_to_shared(&As[s][0][0]);
        const unsigned sB = (unsigned)__cvta_generic_to_shared(&Bs[s][0][0]);
        #pragma unroll
        for (int ks = 0; ks < BK; ks += 8) {
            unsigned af[MT][4];
            #pragma unroll
            for (int im = 0; im < MT; ++im)
                ldsm4(af[im][0], af[im][1], af[im][2], af[im][3],
                      sA + 4u*(aBase + im*16*BKp + ks));
            unsigned bf[NT][2];
            #pragma unroll
            for (int jp = 0; jp < NT/2; ++jp) {
                unsigned r0, r1, r2, r3;
                ldsm4(r0, r1, r2, r3, sB + 4u*(bBase + jp*16*BKp + ks));
                bf[2*jp][0] = r0; bf[2*jp][1] = r1;
                bf[2*jp+1][0] = r2; bf[2*jp+1][1] = r3;
            }
            #pragma unroll
            for (int im = 0; im < MT; ++im)
                #pragma unroll
                for (int jn = 0; jn < NT; ++jn)
                    mma_tf32(acc[im][jn], af[im], bf[jn]);
        }
    };

    gload(0);
    sstore(0);
    __syncthreads();

    for (int kt = 0; kt < ktiles; ++kt) {
        const bool more = (kt + 1 < ktiles);
        if (more) gload((kt+1)*BK);
        compute(kt & 1);
        if (more) sstore((kt+1) & 1);
        __syncthreads();
    }

    #pragma unroll
    for (int im = 0; im < MT; ++im) {
        #pragma unroll
        for (int jn = 0; jn < NT; ++jn) {
            #pragma unroll
            for (int h = 0; h < 2; ++h) {
                const int m = m0 + mw0 + im*16 + qr + h*8;
                const int n = n0 + nw0 + jn*8 + qc*2;
                const long ci = (long)m * ldc + n;
                float v0 = acc[im][jn][h*2 + 0];
                float v1 = acc[im][jn][h*2 + 1];
                if (MODE == 0) {
                    C[ci] = v0; C[ci+1] = v1;
                } else if (MODE == 5) {
                    C[ci]   = 0.5f * v0 * (1.f + erff(v0 * 0.70710678118654752f));
                    C[ci+1] = 0.5f * v1 * (1.f + erff(v1 * 0.70710678118654752f));
                } else if (MODE == 6) {
                    C[ci]   = P1[ci]   * v0 + P2[ci];
                    C[ci+1] = P1[ci+1] * v1 + P2[ci+1];
                } else if (MODE == 7) {
                    C[ci] = v0; C[ci+1] = v1;
                    __nv_bfloat16* Cb = (__nv_bfloat16*)P2;
                    *(__nv_bfloat162*)(Cb + ci) = __floats2bfloat162_rn(v0, v1);
                }
            }
        }
    }
}

// ---------------- pipelined bf16 core (cp.async, 4 stages) ----------
// Tile (MW*32) x 64, MW*64 threads, warps (MW m) x (2 n), warp tile 32x32.
// OPB: 0 = B[N,K] (NT); 1 = B[K,N] (NN).
// MODE: 2 tril mask -> bf16 Ch   3 C=P1a-ETA*acc (tril-K)   4 C=C-ETA*acc
//       11 Ch=bf16(acc-P1a)      12 C=acc (fp32)            14 Ch=bf16(acc)
template<int MW,int OPB,int MODE>
__device__ __forceinline__ void hcore(
    int m0, int n0,
    const __nv_bfloat16* A, long lda,
    const __nv_bfloat16* B, long ldb,
    float* C, __nv_bfloat16* Ch, long ldc, int K,
    const float* P1a, char* sm)
{
    constexpr int BM = MW*32, BK = 16;
    constexpr int ASTG = BM*48;
    constexpr int STG  = ASTG + 3072;
    const int tid = threadIdx.x, lane = tid & 31, wid = tid >> 5;
    const int wm = wid >> 1, wn = wid & 1;
    const int mw0 = wm * 32, nw0 = wn * 32;
    const int qr = lane >> 2, qc = lane & 3;
    const uint32_t sbase = smem_u32(sm);

    float acc[2][4][4];
    #pragma unroll
    for (int i = 0; i < 2; ++i)
        #pragma unroll
        for (int j = 0; j < 4; ++j)
            #pragma unroll
            for (int q = 0; q < 4; ++q) acc[i][j][q] = 0.f;

    int Kl = K;
    if (MODE == 3) { int t = m0 + BM; Kl = t < K ? t : K; }
    const int ktiles = Kl / BK;

    const int arow = tid >> 1, ahalf = tid & 1;    // blockDim == BM*2
    const __nv_bfloat16* Ar = A + (long)(m0 + arow) * lda;

    auto fill = [&](int kt) {
        if (kt < ktiles) {
            const long k0 = (long)kt * BK;
            const uint32_t as = sbase + (kt & 3) * STG;
            const uint32_t bs = as + ASTG;
            cpa16(as + arow*48 + ahalf*16, Ar + k0 + ahalf*8);
            if (MW == 2 || tid < 128) {
                if (OPB == 0) {
                    const int r = tid >> 1, h = tid & 1;
                    cpa16(bs + (r & 63)*48 + h*16, B + (long)(n0 + (r & 63))*ldb + k0 + h*8);
                } else {
                    const int kk = (tid >> 3) & 15, nc = tid & 7;
                    cpa16(bs + kk*144 + nc*16, B + (k0 + kk)*ldb + n0 + nc*8);
                }
            }
        }
        cpa_commit();
    };
    auto compute = [&](int kt) {
        const uint32_t sA = sbase + (kt & 3) * STG;
        const uint32_t sB = sA + ASTG;
        const int g = lane >> 3;
        unsigned af[2][4];
        #pragma unroll
        for (int im = 0; im < 2; ++im) {
            const int row = mw0 + im*16 + (g & 1)*8 + (lane & 7);
            const int kb = (g >> 1)*8;
            ldsm4(af[im][0], af[im][1], af[im][2], af[im][3],
                  sA + (unsigned)(row*48 + kb*2));
        }
        unsigned bf[4][2];
        #pragma unroll
        for (int jp = 0; jp < 2; ++jp) {
            unsigned r0, r1, r2, r3;
            if (OPB == 0) {
                const int row = nw0 + jp*16 + (g >> 1)*8 + (lane & 7);
                const int kb = (g & 1)*8;
                ldsm4(r0, r1, r2, r3, sB + (unsigned)(row*48 + kb*2));
            } else {
                const int krow = (g & 1)*8 + (lane & 7);
                const int col = nw0 + jp*16 + (g >> 1)*8;
                ldsm4t(r0, r1, r2, r3, sB + (unsigned)(krow*144 + col*2));
            }
            bf[2*jp][0] = r0; bf[2*jp][1] = r1;
            bf[2*jp+1][0] = r2; bf[2*jp+1][1] = r3;
        }
        #pragma unroll
        for (int im = 0; im < 2; ++im)
            #pragma unroll
            for (int jn = 0; jn < 4; ++jn)
                mma_bf16(acc[im][jn], af[im], bf[jn]);
    };

    fill(0); fill(1); fill(2);
    for (int kt = 0; kt < ktiles; ++kt) {
        asm volatile("cp.async.wait_group 2;" ::: "memory");
        __syncthreads();
        fill(kt + 3);
        compute(kt);
    }
    asm volatile("cp.async.wait_group 0;" ::: "memory");

    #pragma unroll
    for (int im = 0; im < 2; ++im) {
        #pragma unroll
        for (int jn = 0; jn < 4; ++jn) {
            #pragma unroll
            for (int h = 0; h < 2; ++h) {
                const int m = m0 + mw0 + im*16 + qr + h*8;
                const int n = n0 + nw0 + jn*8 + qc*2;
                const long ci = (long)m * ldc + n;
                float v0 = acc[im][jn][h*2 + 0];
                float v1 = acc[im][jn][h*2 + 1];
                if (MODE == 2) {
                    const bool z = ((n >> 4) > (m >> 4));
                    if (z) { v0 = 0.f; v1 = 0.f; }
                    *(__nv_bfloat162*)(Ch + ci) = __floats2bfloat162_rn(v0, v1);
                } else if (MODE == 3) {
                    float2 p = *(const float2*)(P1a + (long)m * ldc + n);
                    C[ci]   = p.x - ETA_F * v0;
                    C[ci+1] = p.y - ETA_F * v1;
                } else if (MODE == 4) {
                    float2 cc = *(const float2*)(C + ci);
                    C[ci]   = cc.x - ETA_F * v0;
                    C[ci+1] = cc.y - ETA_F * v1;
                } else if (MODE == 11) {
                    float2 p = *(const float2*)(P1a + ci);
                    *(__nv_bfloat162*)(Ch + ci) =
                        __floats2bfloat162_rn(v0 - p.x, v1 - p.y);
                } else if (MODE == 12) {
                    C[ci] = v0; C[ci+1] = v1;
                } else if (MODE == 14) {
                    *(__nv_bfloat162*)(Ch + ci) = __floats2bfloat162_rn(v0, v1);
                }
            }
        }
    }
}

// STATE = HTh @ Wsth^T (fp32 out)
__global__ void __launch_bounds__(256) k_bstate(
    const __nv_bfloat16* __restrict__ HTh, const __nv_bfloat16* __restrict__ Wsth,
    float* __restrict__ ST)
{
    __shared__ __align__(16) char sm[4*(128*48 + 3072)];
    hcore<4,0,12>(blockIdx.y * 128, blockIdx.x * 64, HTh, DD,
                  Wsth, DD, ST, nullptr, DD, DD, nullptr, sm);
}

// ABh = bf16(TVh @ W0h^T - ST)
__global__ void __launch_bounds__(256) k_babh(
    const __nv_bfloat16* __restrict__ TVh, const __nv_bfloat16* __restrict__ W0h,
    const float* __restrict__ ST, __nv_bfloat16* __restrict__ ABh)
{
    __shared__ __align__(16) char sm[4*(128*48 + 3072)];
    hcore<4,0,11>(blockIdx.y * 128, blockIdx.x * 64, TVh, DD,
                  W0h, DD, nullptr, ABh, DD, DD, ST, sm);
}

// Hbh = bf16(trilblk(PRh @ TVh^T)), batched over chunks
__global__ void __launch_bounds__(256) k_gramh(
    const __nv_bfloat16* __restrict__ PRh, const __nv_bfloat16* __restrict__ TVh,
    __nv_bfloat16* __restrict__ Hbh)
{
    const int m0 = blockIdx.y * 128, n0 = blockIdx.x * 64;
    if (n0 >= m0 + 128) return;
    __shared__ __align__(16) char sm[4*(128*48 + 3072)];
    const long z = blockIdx.z;
    hcore<4,0,2>(m0, n0, PRh + z*RR*DD, DD, TVh + z*RR*DD, DD,
                 nullptr, Hbh + z*RR*RR, RR, DD, nullptr, sm);
}

// INC_c = bf16(TVth_c @ ABh_c)  (batched, OPB=1)
__global__ void __launch_bounds__(256) k_oph(
    const __nv_bfloat16* __restrict__ TVth, const __nv_bfloat16* __restrict__ ABh,
    __nv_bfloat16* __restrict__ INC)
{
    __shared__ __align__(16) char sm[4*(128*48 + 3072)];
    const long z = blockIdx.z;
    hcore<4,1,14>(blockIdx.y * 128, blockIdx.x * 64,
                  TVth + z*DD*RR, RR, ABh + z*RR*DD, DD,
                  nullptr, INC + z*DD*DD, DD, RR, nullptr, sm);
}

// OT_c = PB_c - ETA * trilHb_c @ AB_c  (batched, OPB=1, tril-K)
__global__ void __launch_bounds__(256) k_rdtril(
    const __nv_bfloat16* __restrict__ Hbh, const __nv_bfloat16* __restrict__ ABh,
    const float* __restrict__ PB, float* __restrict__ OT)
{
    __shared__ __align__(16) char sm[4*(128*48 + 3072)];
    const long z = blockIdx.z;
    hcore<4,1,3>(blockIdx.y * 128, blockIdx.x * 64,
                 Hbh + z*RR*RR, RR, ABh + z*RR*DD, DD,
                 OT + z*RR*DD, nullptr, DD, RR, PB + z*RR*DD, sm);
}

// OT_{z+1} -= ETA * PR_{z+1} @ St_z  (batched c=1..NC-1, OPB=1)
__global__ void __launch_bounds__(256) k_term1(
    const __nv_bfloat16* __restrict__ PRh, const __nv_bfloat16* __restrict__ St,
    float* __restrict__ OT)
{
    __shared__ __align__(16) char sm[4*(128*48 + 3072)];
    const long z = blockIdx.z;                  // chunk c = z+1
    hcore<4,1,4>(blockIdx.y * 128, blockIdx.x * 64,
                 PRh + (z+1)*RR*DD, DD, St + z*DD*DD, DD,
                 OT + (z+1)*RR*DD, nullptr, DD, DD, nullptr, sm);
}

// ---------------- host side ----------------
extern "C" void kernel_launch(void* const* d_in, const int* in_sizes, int n_in,
                              void* d_out, int out_size) {
    const float* x      = (const float*)d_in[0];
    const float* noise  = (const float*)d_in[1];
    const float* alpha1 = (const float*)d_in[2];
    const float* alpha2 = (const float*)d_in[3];
    const float* W_map  = (const float*)d_in[4];
    const float* W_st   = (const float*)d_in[5];
    const float* W_pr   = (const float*)d_in[6];
    const float* W_p1   = (const float*)d_in[7];
    const float* W_p2   = (const float*)d_in[8];
    float* out = (float*)d_out;

    float *HT, *ST, *PR, *PB, *OT, *X1, *H2, *U;
    __nv_bfloat16 *HTh, *TVh, *TVth, *ABh, *PRh, *Wsth, *W0h, *Hbh, *INC, *St;
    cudaGetSymbolAddress((void**)&HT, g_HT);
    cudaGetSymbolAddress((void**)&ST, g_STATE);
    cudaGetSymbolAddress((void**)&PR, g_PROBE);
    cudaGetSymbolAddress((void**)&PB, g_PBASE);
    cudaGetSymbolAddress((void**)&OT, g_OT);
    cudaGetSymbolAddress((void**)&X1, g_X1);
    cudaGetSymbolAddress((void**)&H2, g_H2);
    cudaGetSymbolAddress((void**)&U,  g_U);
    cudaGetSymbolAddress((void**)&HTh, g_HTh);
    cudaGetSymbolAddress((void**)&TVh, g_TVh);
    cudaGetSymbolAddress((void**)&TVth, g_TVth);
    cudaGetSymbolAddress((void**)&ABh, g_ABh);
    cudaGetSymbolAddress((void**)&PRh, g_PRh);
    cudaGetSymbolAddress((void**)&Wsth, g_Wsth);
    cudaGetSymbolAddress((void**)&W0h, g_W0h);
    cudaGetSymbolAddress((void**)&Hbh, g_Hbh);
    cudaGetSymbolAddress((void**)&INC, g_INC);
    cudaGetSymbolAddress((void**)&St,  g_St);

    const int EW_BLKS = (SB*DD/4) / 256;

    // 0: bf16 weight copies
    k_cvt<<<(DD*DD/4)/256, 256>>>(W_st, Wsth, W_map, W0h);
    // 1: h = tanh(alpha1*x), time-major (fp32 + bf16)
    k_prep<<<EW_BLKS, 256>>>(x, alpha1, HT, HTh);
    // 2: STATE = HTh@Wsth^T (bf16 engine, fp32 out)
    k_bstate<<<dim3(DD/64, SB/128), 256>>>(HTh, Wsth, ST);
    // 3: TVh = bf16(STATE + noise)
    k_tv<<<EW_BLKS, 256>>>(ST, noise, TVh);
    // 4: TVth = per-chunk transpose of TVh
    k_trb<<<dim3(DD/32, RR/32, NC), dim3(32,8)>>>(TVh, TVth);
    // 5: ABh = bf16(TVh@W0h^T - STATE)
    k_babh<<<dim3(DD/64, SB/128), 256>>>(TVh, W0h, ST, ABh);
    // 6: PROBE = HT@Wpr^T (tf32, fp32 + bf16)
    gemm_t<128,128,2,4,7><<<dim3(DD/128, SB/128), 256>>>(
        HT, DD, W_pr, DD, PR, DD, DD, nullptr, (const float*)PRh);
    // 7: PBASE = PROBE@W0^T (tf32)
    gemm_t<128,128,2,4,0><<<dim3(DD/128, SB/128), 256>>>(
        PR, DD, W_map, DD, PB, DD, DD, nullptr, nullptr);
    // 8: cross-Gram -> Hbh (batched)
    k_gramh<<<dim3(RR/64, RR/128, NC), 256>>>(PRh, TVh, Hbh);
    // 9: INC_c = TVth_c @ ABh_c (batched)
    k_oph<<<dim3(DD/64, DD/128, NC), 256>>>(TVth, ABh, INC);
    // 10: prefix scan over chunks
    k_scan<<<(DD*DD/2)/256, 256>>>(INC, St);
    // 11: OT = PB - ETA*trilHb@AB (batched)
    k_rdtril<<<dim3(DD/64, RR/128, NC), 256>>>(Hbh, ABh, PB, OT);
    // 12: OT_c -= ETA*PR_c@St_{c-1} (batched, c>=1)
    k_term1<<<dim3(DD/64, RR/128, NC-1), 256>>>(PRh, St, OT);
    // 13: x1 / h2
    k_x1h2<<<EW_BLKS, 256>>>(OT, x, alpha2, X1, H2);
    // 14: U = gelu(h2 @ Wp1^T) (tf32)
    gemm_t<128,128,2,4,5><<<dim3(DD/128, SB/128), 256>>>(
        H2, DD, W_p1, DD, U, DD, DD, nullptr, nullptr);
    // 15: out = U * (h2 @ Wp2^T) + X1 (tf32)
    gemm_t<128,128,2,4,6><<<dim3(DD/128, SB/128), 256>>>(
        H2, DD, W_p2, DD, out, DD, DD, U, X1);
}

// round 14
// speedup vs baseline: 1.1852x; 1.1852x over previous
#include <cuda_runtime.h>
#include <cuda_bf16.h>
#include <math.h>
#include <stdint.h>

#define BB 16
#define SS 1024
#define DD 1024
#define CH 32
#define RR 512            // CH*BB rows per chunk
#define NC 32             // SS/CH chunks
#define SB (SS*BB)        // 16384 rows total
#define ETA_F (0.01f*2.0f/(16.0f*1024.0f))

// ---------------- device scratch ----------------
__device__ float g_HT[SB*DD];
__device__ float g_STATE[SB*DD];
__device__ float g_PROBE[SB*DD];
__device__ float g_PBASE[SB*DD];   // PROBE@W0^T (all chunks)
__device__ float g_OT[SB*DD];
__device__ float g_X1[SB*DD];
__device__ float g_U[SB*DD];
__device__ float g_UW[DD*DD];      // accumulated A^T TV (fp32 master)
__device__ float g_P[RR*DD];       // per-chunk corrected P (fp32)
__device__ __nv_bfloat16 g_HTh[SB*DD];
__device__ __nv_bfloat16 g_TVh[SB*DD];
__device__ __nv_bfloat16 g_ABh[SB*DD];   // base A = TV@W0^T - STATE (bf16)
__device__ __nv_bfloat16 g_PRh[SB*DD];
__device__ __nv_bfloat16 g_H2h[SB*DD];
__device__ __nv_bfloat16 g_UWh[DD*DD];
__device__ __nv_bfloat16 g_Wsth[DD*DD];
__device__ __nv_bfloat16 g_W0h[DD*DD];
__device__ __nv_bfloat16 g_Wp1h[DD*DD];
__device__ __nv_bfloat16 g_Wp2h[DD*DD];
__device__ __nv_bfloat16 g_Ah[RR*DD];    // corrected A (bf16, row-major)
__device__ __nv_bfloat16 g_Ath[DD*RR];   // corrected A transposed
__device__ __nv_bfloat16 g_Hbh[(long)NC*RR*RR];

// ---------------- helpers ----------------
__device__ __forceinline__ float tf32r(float x) {
    unsigned u;
    asm("cvt.rna.tf32.f32 %0, %1;" : "=r"(u) : "f"(x));
    return __uint_as_float(u);
}
__device__ __forceinline__ uint32_t smem_u32(const void* p) {
    uint32_t a;
    asm("{ .reg .u64 t; cvta.to.shared.u64 t, %1; cvt.u32.u64 %0, t; }"
        : "=r"(a) : "l"(p));
    return a;
}
__device__ __forceinline__ void cpa16(uint32_t d, const void* g) {
    asm volatile("cp.async.cg.shared.global [%0], [%1], 16;" :: "r"(d), "l"(g));
}
__device__ __forceinline__ void cpa_commit() {
    asm volatile("cp.async.commit_group;" ::: "memory");
}
__device__ __forceinline__ void mma_tf32(float* c, const unsigned* a, const unsigned* b) {
    asm volatile(
        "mma.sync.aligned.m16n8k8.row.col.f32.tf32.tf32.f32 "
        "{%0,%1,%2,%3}, {%4,%5,%6,%7}, {%8,%9}, {%0,%1,%2,%3};\n"
        : "+f"(c[0]), "+f"(c[1]), "+f"(c[2]), "+f"(c[3])
        : "r"(a[0]), "r"(a[1]), "r"(a[2]), "r"(a[3]), "r"(b[0]), "r"(b[1]));
}
__device__ __forceinline__ void mma_bf16(float* c, const unsigned* a, const unsigned* b) {
    asm volatile(
        "mma.sync.aligned.m16n8k16.row.col.f32.bf16.bf16.f32 "
        "{%0,%1,%2,%3}, {%4,%5,%6,%7}, {%8,%9}, {%0,%1,%2,%3};\n"
        : "+f"(c[0]), "+f"(c[1]), "+f"(c[2]), "+f"(c[3])
        : "r"(a[0]), "r"(a[1]), "r"(a[2]), "r"(a[3]), "r"(b[0]), "r"(b[1]));
}
__device__ __forceinline__ void ldsm4(unsigned& r0, unsigned& r1, unsigned& r2,
                                      unsigned& r3, unsigned addr) {
    asm volatile("ldmatrix.sync.aligned.m8n8.x4.shared.b16 {%0,%1,%2,%3},[%4];"
                 : "=r"(r0), "=r"(r1), "=r"(r2), "=r"(r3) : "r"(addr));
}
__device__ __forceinline__ void ldsm4t(unsigned& r0, unsigned& r1, unsigned& r2,
                                       unsigned& r3, unsigned addr) {
    asm volatile("ldmatrix.sync.aligned.m8n8.x4.trans.shared.b16 {%0,%1,%2,%3},[%4];"
                 : "=r"(r0), "=r"(r1), "=r"(r2), "=r"(r3) : "r"(addr));
}

// ---------------- elementwise kernels ----------------
__global__ void k_cvt(const float* __restrict__ a, __nv_bfloat16* __restrict__ ah,
                      const float* __restrict__ b, __nv_bfloat16* __restrict__ bh) {
    long i = (long)blockIdx.x * blockDim.x + threadIdx.x;
    float4 v = *(const float4*)(a + i*4);
    *(__nv_bfloat162*)(ah + i*4)     = __floats2bfloat162_rn(v.x, v.y);
    *(__nv_bfloat162*)(ah + i*4 + 2) = __floats2bfloat162_rn(v.z, v.w);
    float4 w = *(const float4*)(b + i*4);
    *(__nv_bfloat162*)(bh + i*4)     = __floats2bfloat162_rn(w.x, w.y);
    *(__nv_bfloat162*)(bh + i*4 + 2) = __floats2bfloat162_rn(w.z, w.w);
}

__global__ void k_prep(const float* __restrict__ x, const float* __restrict__ a1,
                       float* __restrict__ HT, __nv_bfloat16* __restrict__ HTh) {
    long i4 = (long)blockIdx.x * blockDim.x + threadIdx.x;
    long flat = i4 * 4;
    int b = (int)(flat / ((long)SS*DD));
    int t = (int)((flat / DD) % SS);
    int d = (int)(flat % DD);
    float4 xv = *(const float4*)(x + flat);
    float4 av = *(const float4*)(a1 + d);
    float4 o;
    o.x = tanhf(av.x * xv.x); o.y = tanhf(av.y * xv.y);
    o.z = tanhf(av.z * xv.z); o.w = tanhf(av.w * xv.w);
    const long di = (long)(t*BB + b) * DD + d;
    *(float4*)(HT + di) = o;
    *(__nv_bfloat162*)(HTh + di)     = __floats2bfloat162_rn(o.x, o.y);
    *(__nv_bfloat162*)(HTh + di + 2) = __floats2bfloat162_rn(o.z, o.w);
}

__global__ void k_tv(const float* __restrict__ ST, const float* __restrict__ noise,
                     __nv_bfloat16* __restrict__ TVh) {
    long i4 = (long)blockIdx.x * blockDim.x + threadIdx.x;
    long flat = i4 * 4;
    int t = (int)(flat / ((long)BB*DD));
    int b = (int)((flat / DD) % BB);
    int d = (int)(flat % DD);
    float4 s = *(const float4*)(ST + flat);
    float4 n = *(const float4*)(noise + ((long)b*SS + t) * DD + d);
    *(__nv_bfloat162*)(TVh + flat)     = __floats2bfloat162_rn(s.x+n.x, s.y+n.y);
    *(__nv_bfloat162*)(TVh + flat + 2) = __floats2bfloat162_rn(s.z+n.z, s.w+n.w);
}

__global__ void k_zero(float* __restrict__ a, __nv_bfloat16* __restrict__ ah) {
    long i = (long)blockIdx.x * blockDim.x + threadIdx.x;
    *(float4*)(a + i*4) = make_float4(0.f, 0.f, 0.f, 0.f);
    *(float2*)((float*)(ah + i*4)) = make_float2(0.f, 0.f);
}

__global__ void k_x1h2(const float* __restrict__ OT, const float* __restrict__ x,
                       const float* __restrict__ a2,
                       float* __restrict__ X1, __nv_bfloat16* __restrict__ H2h) {
    long i4 = (long)blockIdx.x * blockDim.x + threadIdx.x;
    long flat = i4 * 4;
    int b = (int)(flat / ((long)SS*DD));
    int t = (int)((flat / DD) % SS);
    int d = (int)(flat % DD);
    float4 ro = *(const float4*)(OT + ((long)(t*BB + b) * DD + d));
    float4 xv = *(const float4*)(x + flat);
    float4 av = *(const float4*)(a2 + d);
    float4 x1; x1.x = ro.x+xv.x; x1.y = ro.y+xv.y; x1.z = ro.z+xv.z; x1.w = ro.w+xv.w;
    *(float4*)(X1 + flat) = x1;
    float h0 = tanhf(av.x*x1.x), h1 = tanhf(av.y*x1.y);
    float h2 = tanhf(av.z*x1.z), h3 = tanhf(av.w*x1.w);
    *(__nv_bfloat162*)(H2h + flat)     = __floats2bfloat162_rn(h0, h1);
    *(__nv_bfloat162*)(H2h + flat + 2) = __floats2bfloat162_rn(h2, h3);
}

// ---------------- tf32 tensor-core GEMM (direct-precision paths) ----------
// MODE: 0 plain  7 plain + bf16 copy->P2
template<int BM,int BN,int MW,int NW,int MODE>
__global__ void __launch_bounds__(MW*NW*32, 2)
gemm_t(const float* __restrict__ A, int lda,
       const float* __restrict__ B, int ldb,
       float* __restrict__ C, int ldc, int K,
       const float* __restrict__ P1, const float* __restrict__ P2)
{
    constexpr int BK  = 16;
    constexpr int BKp = 20;
    constexpr int T   = MW*NW*32;
    constexpr int WM  = BM/MW, WN = BN/NW;
    constexpr int MT  = WM/16, NT = WN/8;
    constexpr int LPA = BM*BK/(4*T);
    constexpr int LPB = BN*BK/(4*T);

    const int m0 = blockIdx.y * BM, n0 = blockIdx.x * BN;

    __shared__ __align__(16) float As[2][BM][BKp];
    __shared__ __align__(16) float Bs[2][BN][BKp];

    const int tid  = threadIdx.x;
    const int lane = tid & 31;
    const int wid  = tid >> 5;
    const int wm   = wid / NW, wn = wid % NW;
    const int mw0  = wm * WM, nw0 = wn * WN;
    const int qr   = lane >> 2;
    const int qc   = lane & 3;
    const int lr   = lane & 7;
    const int aBase = (mw0 + lr + ((lane>>3)&1)*8) * BKp + ((lane>>4)&1)*4;
    const int bBase = (nw0 + lr + ((lane>>4)&1)*8) * BKp + ((lane>>3)&1)*4;

    float acc[MT][NT][4];
    #pragma unroll
    for (int i = 0; i < MT; ++i)
        #pragma unroll
        for (int j = 0; j < NT; ++j)
            #pragma unroll
            for (int q = 0; q < 4; ++q) acc[i][j][q] = 0.f;

    const int ktiles = K / BK;
    float4 pa[LPA], pb[LPB];

    auto gload = [&](int k0) {
        #pragma unroll
        for (int p = 0; p < LPA; ++p) {
            const int idx = tid + p*T;
            const int am = idx / (BK/4), akq = idx % (BK/4);
            pa[p] = *(const float4*)(A + (long)(m0 + am) * lda + k0 + 4*akq);
        }
        #pragma unroll
        for (int p = 0; p < LPB; ++p) {
            const int idx = tid + p*T;
            const int bn = idx / (BK/4), bkq = idx % (BK/4);
            pb[p] = *(const float4*)(B + (long)(n0 + bn) * ldb + k0 + 4*bkq);
        }
    };
    auto sstore = [&](int s) {
        #pragma unroll
        for (int p = 0; p < LPA; ++p) {
            const int idx = tid + p*T;
            const int am = idx / (BK/4), akq = idx % (BK/4);
            float4 w = make_float4(tf32r(pa[p].x), tf32r(pa[p].y),
                                   tf32r(pa[p].z), tf32r(pa[p].w));
            *(float4*)&As[s][am][4*akq] = w;
        }
        #pragma unroll
        for (int p = 0; p < LPB; ++p) {
            const int idx = tid + p*T;
            const int bn = idx / (BK/4), bkq = idx % (BK/4);
            float4 w = make_float4(tf32r(pb[p].x), tf32r(pb[p].y),
                                   tf32r(pb[p].z), tf32r(pb[p].w));
            *(float4*)&Bs[s][bn][4*bkq] = w;
        }
    };
    auto compute = [&](int s) {
        const unsigned sA = (unsigned)__cvta_generic_to_shared(&As[s][0][0]);
        const unsigned sB = (unsigned)__cvta_generic_to_shared(&Bs[s][0][0]);
        #pragma unroll
        for (int ks = 0; ks < BK; ks += 8) {
            unsigned af[MT][4];
            #pragma unroll
            for (int im = 0; im < MT; ++im)
                ldsm4(af[im][0], af[im][1], af[im][2], af[im][3],
                      sA + 4u*(aBase + im*16*BKp + ks));
            unsigned bf[NT][2];
            #pragma unroll
            for (int jp = 0; jp < NT/2; ++jp) {
                unsigned r0, r1, r2, r3;
                ldsm4(r0, r1, r2, r3, sB + 4u*(bBase + jp*16*BKp + ks));
                bf[2*jp][0] = r0; bf[2*jp][1] = r1;
                bf[2*jp+1][0] = r2; bf[2*jp+1][1] = r3;
            }
            #pragma unroll
            for (int im = 0; im < MT; ++im)
                #pragma unroll
                for (int jn = 0; jn < NT; ++jn)
                    mma_tf32(acc[im][jn], af[im], bf[jn]);
        }
    };

    gload(0);
    sstore(0);
    __syncthreads();

    for (int kt = 0; kt < ktiles; ++kt) {
        const bool more = (kt + 1 < ktiles);
        if (more) gload((kt+1)*BK);
        compute(kt & 1);
        if (more) sstore((kt+1) & 1);
        __syncthreads();
    }

    #pragma unroll
    for (int im = 0; im < MT; ++im) {
        #pragma unroll
        for (int jn = 0; jn < NT; ++jn) {
            #pragma unroll
            for (int h = 0; h < 2; ++h) {
                const int m = m0 + mw0 + im*16 + qr + h*8;
                const int n = n0 + nw0 + jn*8 + qc*2;
                const long ci = (long)m * ldc + n;
                float v0 = acc[im][jn][h*2 + 0];
                float v1 = acc[im][jn][h*2 + 1];
                if (MODE == 0) {
                    C[ci] = v0; C[ci+1] = v1;
                } else if (MODE == 7) {
                    C[ci] = v0; C[ci+1] = v1;
                    __nv_bfloat16* Cb = (__nv_bfloat16*)P2;
                    *(__nv_bfloat162*)(Cb + ci) = __floats2bfloat162_rn(v0, v1);
                }
            }
        }
    }
}

// ---------------- pipelined bf16 core (cp.async, 4 stages) ----------
// Tile (MW*32) x 64, MW*64 threads, warps (MW m) x (2 n), warp tile 32x32.
// OPA: 0 = A[M,K]; 2 = dual-source rows. OPB: 0 = B[N,K]; 1 = B[K,N].
// MODE: 2 tril mask -> bf16 Ch     3 C=P1a-ETA*acc (tril-K)
//       9 C+=acc & bf16->Ch        10 corr: A rows -> Ch/Ct bf16 (base=Bb),
//                                      P rows -> C fp32 (base=P1b)
//       11 Ch = bf16(acc - P1a)    12 C = acc (fp32)
//       15 C = gelu(acc) (fp32)    16 C = P1a*acc + P1b (fp32)
template<int MW,int OPA,int OPB,int MODE>
__device__ __forceinline__ void hcore(
    int m0, int n0,
    const __nv_bfloat16* A, const __nv_bfloat16* A2, long lda,
    const __nv_bfloat16* B, long ldb,
    float* C, __nv_bfloat16* Ch, __nv_bfloat16* Ct, long ldc, int K,
    const float* P1a, const float* P1b, const __nv_bfloat16* Bb, char* sm)
{
    constexpr int BM = MW*32, BK = 16;
    constexpr int ASTG = BM*48;
    constexpr int STG  = ASTG + 3072;
    const int tid = threadIdx.x, lane = tid & 31, wid = tid >> 5;
    const int wm = wid >> 1, wn = wid & 1;
    const int mw0 = wm * 32, nw0 = wn * 32;
    const int qr = lane >> 2, qc = lane & 3;
    const uint32_t sbase = smem_u32(sm);

    float acc[2][4][4];
    #pragma unroll
    for (int i = 0; i < 2; ++i)
        #pragma unroll
        for (int j = 0; j < 4; ++j)
            #pragma unroll
            for (int q = 0; q < 4; ++q) acc[i][j][q] = 0.f;

    int Kl = K;
    if (MODE == 3) { int t = m0 + BM; Kl = t < K ? t : K; }
    const int ktiles = Kl / BK;

    const int arow = tid >> 1, ahalf = tid & 1;    // blockDim == BM*2
    const int mg = m0 + arow;
    const __nv_bfloat16* Ar;
    if (OPA == 2) Ar = (mg < RR) ? (A + (long)mg * lda)
                                 : (A2 + (long)(mg - RR) * lda);
    else          Ar = A + (long)mg * lda;

    auto fill = [&](int kt) {
        if (kt < ktiles) {
            const long k0 = (long)kt * BK;
            const uint32_t as = sbase + (kt & 3) * STG;
            const uint32_t bs = as + ASTG;
            cpa16(as + arow*48 + ahalf*16, Ar + k0 + ahalf*8);
            if (MW == 2 || tid < 128) {
                if (OPB == 0) {
                    const int r = tid >> 1, h = tid & 1;
                    cpa16(bs + (r & 63)*48 + h*16, B + (long)(n0 + (r & 63))*ldb + k0 + h*8);
                } else {
                    const int kk = (tid >> 3) & 15, nc = tid & 7;
                    cpa16(bs + kk*144 + nc*16, B + (k0 + kk)*ldb + n0 + nc*8);
                }
            }
        }
        cpa_commit();
    };
    auto compute = [&](int kt) {
        const uint32_t sA = sbase + (kt & 3) * STG;
        const uint32_t sB = sA + ASTG;
        const int g = lane >> 3;
        unsigned af[2][4];
        #pragma unroll
        for (int im = 0; im < 2; ++im) {
            const int row = mw0 + im*16 + (g & 1)*8 + (lane & 7);
            const int kb = (g >> 1)*8;
            ldsm4(af[im][0], af[im][1], af[im][2], af[im][3],
                  sA + (unsigned)(row*48 + kb*2));
        }
        unsigned bf[4][2];
        #pragma unroll
        for (int jp = 0; jp < 2; ++jp) {
            unsigned r0, r1, r2, r3;
            if (OPB == 0) {
                const int row = nw0 + jp*16 + (g >> 1)*8 + (lane & 7);
                const int kb = (g & 1)*8;
                ldsm4(r0, r1, r2, r3, sB + (unsigned)(row*48 + kb*2));
            } else {
                const int krow = (g & 1)*8 + (lane & 7);
                const int col = nw0 + jp*16 + (g >> 1)*8;
                ldsm4t(r0, r1, r2, r3, sB + (unsigned)(krow*144 + col*2));
            }
            bf[2*jp][0] = r0; bf[2*jp][1] = r1;
            bf[2*jp+1][0] = r2; bf[2*jp+1][1] = r3;
        }
        #pragma unroll
        for (int im = 0; im < 2; ++im)
            #pragma unroll
            for (int jn = 0; jn < 4; ++jn)
                mma_bf16(acc[im][jn], af[im], bf[jn]);
    };

    fill(0); fill(1); fill(2);
    for (int kt = 0; kt < ktiles; ++kt) {
        asm volatile("cp.async.wait_group 2;" ::: "memory");
        __syncthreads();
        fill(kt + 3);
        compute(kt);
    }
    asm volatile("cp.async.wait_group 0;" ::: "memory");

    #pragma unroll
    for (int im = 0; im < 2; ++im) {
        #pragma unroll
        for (int jn = 0; jn < 4; ++jn) {
            #pragma unroll
            for (int h = 0; h < 2; ++h) {
                const int m = m0 + mw0 + im*16 + qr + h*8;
                const int n = n0 + nw0 + jn*8 + qc*2;
                const long ci = (long)m * ldc + n;
                float v0 = acc[im][jn][h*2 + 0];
                float v1 = acc[im][jn][h*2 + 1];
                if (MODE == 2) {
                    const bool z = ((n >> 4) > (m >> 4));
                    if (z) { v0 = 0.f; v1 = 0.f; }
                    *(__nv_bfloat162*)(Ch + ci) = __floats2bfloat162_rn(v0, v1);
                } else if (MODE == 3) {
                    float2 p = *(const float2*)(P1a + (long)m * ldc + n);
                    C[ci]   = p.x - ETA_F * v0;
                    C[ci+1] = p.y - ETA_F * v1;
                } else if (MODE == 9) {
                    float2 c = *(const float2*)(C + ci);
                    float w0 = c.x + v0, w1 = c.y + v1;
                    C[ci] = w0; C[ci+1] = w1;
                    *(__nv_bfloat162*)(Ch + ci) = __floats2bfloat162_rn(w0, w1);
                } else if (MODE == 10) {
                    if (m < RR) {
                        float b0 = __bfloat162float(Bb[(long)m * DD + n]);
                        float b1 = __bfloat162float(Bb[(long)m * DD + n + 1]);
                        float w0 = b0 - ETA_F * v0, w1 = b1 - ETA_F * v1;
                        *(__nv_bfloat162*)(Ch + (long)m * DD + n) =
                            __floats2bfloat162_rn(w0, w1);
                        Ct[(long)n * RR + m]       = __float2bfloat16(w0);
                        Ct[(long)(n + 1) * RR + m] = __float2bfloat16(w1);
                    } else {
                        const long pi = (long)(m - RR) * DD + n;
                        float2 p = *(const float2*)(P1b + pi);
                        C[pi]     = p.x - ETA_F * v0;
                        C[pi + 1] = p.y - ETA_F * v1;
                    }
                } else if (MODE == 11) {
                    float2 p = *(const float2*)(P1a + ci);
                    *(__nv_bfloat162*)(Ch + ci) =
                        __floats2bfloat162_rn(v0 - p.x, v1 - p.y);
                } else if (MODE == 12) {
                    C[ci] = v0; C[ci+1] = v1;
                } else if (MODE == 15) {
                    C[ci]   = 0.5f * v0 * (1.f + erff(v0 * 0.70710678118654752f));
                    C[ci+1] = 0.5f * v1 * (1.f + erff(v1 * 0.70710678118654752f));
                } else if (MODE == 16) {
                    float2 p = *(const float2*)(P1a + ci);
                    float2 q = *(const float2*)(P1b + ci);
                    C[ci]   = p.x * v0 + q.x;
                    C[ci+1] = p.y * v1 + q.y;
                }
            }
        }
    }
}

// STATE = HTh @ Wsth^T (fp32 out)
__global__ void __launch_bounds__(256) k_bstate(
    const __nv_bfloat16* __restrict__ HTh, const __nv_bfloat16* __restrict__ Wsth,
    float* __restrict__ ST)
{
    __shared__ __align__(16) char sm[4*(128*48 + 3072)];
    hcore<4,0,0,12>(blockIdx.y * 128, blockIdx.x * 64, HTh, nullptr, DD,
                    Wsth, DD, ST, nullptr, nullptr, DD, DD,
                    nullptr, nullptr, nullptr, sm);
}

// ABh = bf16(TVh @ W0h^T - ST)
__global__ void __launch_bounds__(256) k_babh(
    const __nv_bfloat16* __restrict__ TVh, const __nv_bfloat16* __restrict__ W0h,
    const float* __restrict__ ST, __nv_bfloat16* __restrict__ ABh)
{
    __shared__ __align__(16) char sm[4*(128*48 + 3072)];
    hcore<4,0,0,11>(blockIdx.y * 128, blockIdx.x * 64, TVh, nullptr, DD,
                    W0h, DD, nullptr, ABh, nullptr, DD, DD,
                    ST, nullptr, nullptr, sm);
}

// Hbh = bf16(trilblk(PRh @ TVh^T)), batched over chunks
__global__ void __launch_bounds__(256) k_gramh(
    const __nv_bfloat16* __restrict__ PRh, const __nv_bfloat16* __restrict__ TVh,
    __nv_bfloat16* __restrict__ Hbh)
{
    const int m0 = blockIdx.y * 128, n0 = blockIdx.x * 64;
    if (n0 >= m0 + 128) return;
    __shared__ __align__(16) char sm[4*(128*48 + 3072)];
    const long z = blockIdx.z;
    hcore<4,0,0,2>(m0, n0, PRh + z*RR*DD, nullptr, DD, TVh + z*RR*DD, DD,
                   nullptr, Hbh + z*RR*RR, nullptr, RR, DD,
                   nullptr, nullptr, nullptr, sm);
}

// U = gelu(H2h @ Wp1h^T) (fp32 out)
__global__ void __launch_bounds__(256) k_bgelu(
    const __nv_bfloat16* __restrict__ H2h, const __nv_bfloat16* __restrict__ Wp1h,
    float* __restrict__ U)
{
    __shared__ __align__(16) char sm[4*(128*48 + 3072)];
    hcore<4,0,0,15>(blockIdx.y * 128, blockIdx.x * 64, H2h, nullptr, DD,
                    Wp1h, DD, U, nullptr, nullptr, DD, DD,
                    nullptr, nullptr, nullptr, sm);
}

// out = U * (H2h @ Wp2h^T) + X1 (fp32 out)
__global__ void __launch_bounds__(256) k_bout(
    const __nv_bfloat16* __restrict__ H2h, const __nv_bfloat16* __restrict__ Wp2h,
    float* __restrict__ C, const float* __restrict__ U, const float* __restrict__ X1)
{
    __shared__ __align__(16) char sm[4*(128*48 + 3072)];
    hcore<4,0,0,16>(blockIdx.y * 128, blockIdx.x * 64, H2h, nullptr, DD,
                    Wp2h, DD, C, nullptr, nullptr, DD, DD,
                    U, X1, nullptr, sm);
}

// corr: A rows -> Ah/Ath bf16 (base ABh - ETA*TV@UW^T),
//       P rows -> Pbuf fp32 (base PB - ETA*PR@UW^T)
__global__ void __launch_bounds__(128) k_corr64(
    const __nv_bfloat16* __restrict__ TVhc, const __nv_bfloat16* __restrict__ PRhc,
    const __nv_bfloat16* __restrict__ UWh, float* __restrict__ Pbuf,
    __nv_bfloat16* __restrict__ Ah, __nv_bfloat16* __restrict__ Ath,
    const __nv_bfloat16* __restrict__ ABhc, const float* __restrict__ PBc)
{
    __shared__ __align__(16) char sm[4*(64*48 + 3072)];
    hcore<2,2,0,10>(blockIdx.y * 64, blockIdx.x * 64,
                    TVhc, PRhc, DD, UWh, DD,
                    Pbuf, Ah, Ath, DD, DD, nullptr, PBc, ABhc, sm);
}

// merged readout (y<8) + UW update (y>=8)
__global__ void __launch_bounds__(128) k_rduw64(
    const __nv_bfloat16* __restrict__ Hb, const __nv_bfloat16* __restrict__ Ah,
    float* __restrict__ OTc, const float* __restrict__ Pbuf,
    const __nv_bfloat16* __restrict__ Ath, const __nv_bfloat16* __restrict__ TVhc,
    float* __restrict__ UW, __nv_bfloat16* __restrict__ UWh)
{
    __shared__ __align__(16) char sm[4*(64*48 + 3072)];
    const int n0 = blockIdx.x * 64;
    if (blockIdx.y < 8) {
        // OT = P - ETA * trilHb @ A
        hcore<2,0,1,3>(blockIdx.y * 64, n0, Hb, nullptr, RR, Ah, DD,
                       OTc, nullptr, nullptr, DD, RR,
                       Pbuf, nullptr, nullptr, sm);
    } else {
        // UW += A^T @ TVc
        hcore<2,0,1,9>((blockIdx.y - 8) * 64, n0, Ath, nullptr, RR, TVhc, DD,
                       UW, UWh, nullptr, DD, RR,
                       nullptr, nullptr, nullptr, sm);
    }
}

// ---------------- host side ----------------
extern "C" void kernel_launch(void* const* d_in, const int* in_sizes, int n_in,
                              void* d_out, int out_size) {
    const float* x      = (const float*)d_in[0];
    const float* noise  = (const float*)d_in[1];
    const float* alpha1 = (const float*)d_in[2];
    const float* alpha2 = (const float*)d_in[3];
    const float* W_map  = (const float*)d_in[4];
    const float* W_st   = (const float*)d_in[5];
    const float* W_pr   = (const float*)d_in[6];
    const float* W_p1   = (const float*)d_in[7];
    const float* W_p2   = (const float*)d_in[8];
    float* out = (float*)d_out;

    float *HT, *ST, *PR, *PB, *OT, *X1, *U, *UW, *Pbuf;
    __nv_bfloat16 *HTh, *TVh, *ABh, *PRh, *H2h, *UWh, *Wsth, *W0h, *Wp1h, *Wp2h,
                  *Ah, *Ath, *Hbh;
    cudaGetSymbolAddress((void**)&HT, g_HT);
    cudaGetSymbolAddress((void**)&ST, g_STATE);
    cudaGetSymbolAddress((void**)&PR, g_PROBE);
    cudaGetSymbolAddress((void**)&PB, g_PBASE);
    cudaGetSymbolAddress((void**)&OT, g_OT);
    cudaGetSymbolAddress((void**)&X1, g_X1);
    cudaGetSymbolAddress((void**)&U,  g_U);
    cudaGetSymbolAddress((void**)&UW, g_UW);
    cudaGetSymbolAddress((void**)&Pbuf, g_P);
    cudaGetSymbolAddress((void**)&HTh, g_HTh);
    cudaGetSymbolAddress((void**)&TVh, g_TVh);
    cudaGetSymbolAddress((void**)&ABh, g_ABh);
    cudaGetSymbolAddress((void**)&PRh, g_PRh);
    cudaGetSymbolAddress((void**)&H2h, g_H2h);
    cudaGetSymbolAddress((void**)&UWh, g_UWh);
    cudaGetSymbolAddress((void**)&Wsth, g_Wsth);
    cudaGetSymbolAddress((void**)&W0h, g_W0h);
    cudaGetSymbolAddress((void**)&Wp1h, g_Wp1h);
    cudaGetSymbolAddress((void**)&Wp2h, g_Wp2h);
    cudaGetSymbolAddress((void**)&Ah,  g_Ah);
    cudaGetSymbolAddress((void**)&Ath, g_Ath);
    cudaGetSymbolAddress((void**)&Hbh, g_Hbh);

    const int EW_BLKS = (SB*DD/4) / 256;

    // 0: bf16 weight copies
    k_cvt<<<(DD*DD/4)/256, 256>>>(W_st, Wsth, W_map, W0h);
    k_cvt<<<(DD*DD/4)/256, 256>>>(W_p1, Wp1h, W_p2, Wp2h);
    // 1: h = tanh(alpha1*x), time-major (fp32 + bf16)
    k_prep<<<EW_BLKS, 256>>>(x, alpha1, HT, HTh);
    // 2: zero UW
    k_zero<<<(DD*DD/4)/256, 256>>>(UW, UWh);
    // 3: STATE = HTh@Wsth^T (bf16 engine, fp32 out)
    k_bstate<<<dim3(DD/64, SB/128), 256>>>(HTh, Wsth, ST);
    // 4: TVh = bf16(STATE + noise)
    k_tv<<<EW_BLKS, 256>>>(ST, noise, TVh);
    // 5: ABh = bf16(TVh@W0h^T - STATE)
    k_babh<<<dim3(DD/64, SB/128), 256>>>(TVh, W0h, ST, ABh);
    // 6: PROBE = HT@Wpr^T (tf32, fp32 + bf16)  [direct path: stays tf32]
    gemm_t<128,128,2,4,7><<<dim3(DD/128, SB/128), 256>>>(
        HT, DD, W_pr, DD, PR, DD, DD, nullptr, (const float*)PRh);
    // 7: PBASE = PROBE@W0^T (tf32)  [direct path: stays tf32]
    gemm_t<128,128,2,4,0><<<dim3(DD/128, SB/128), 256>>>(
        PR, DD, W_map, DD, PB, DD, DD, nullptr, nullptr);
    // 8: cross-Gram -> Hbh
    k_gramh<<<dim3(RR/64, RR/128, NC), 256>>>(PRh, TVh, Hbh);

    // chunk loop — 2 bf16 GEMM launches per chunk
    for (int c = 0; c < NC; ++c) {
        const __nv_bfloat16* TVhc = TVh + (long)c*RR*DD;
        const __nv_bfloat16* PRhc = PRh + (long)c*RR*DD;
        k_corr64<<<dim3(DD/64, (2*RR)/64), 128>>>(
            TVhc, PRhc, UWh, Pbuf, Ah, Ath,
            ABh + (long)c*RR*DD, PB + (long)c*RR*DD);
        k_rduw64<<<dim3(DD/64, 24), 128>>>(
            Hbh + (long)c*RR*RR, Ah, OT + (long)c*RR*DD, Pbuf,
            Ath, TVhc, UW, UWh);
    }

    // x1 fp32 / h2 bf16
    k_x1h2<<<EW_BLKS, 256>>>(OT, x, alpha2, X1, H2h);
    // U = gelu(h2 @ Wp1^T)  (bf16 engine)
    k_bgelu<<<dim3(DD/64, SB/128), 256>>>(H2h, Wp1h, U);
    // out = U * (h2 @ Wp2^T) + X1  (bf16 engine)
    k_bout<<<dim3(DD/64, SB/128), 256>>>(H2h, Wp2h, out, U, X1);
}

// round 15
// speedup vs baseline: 1.2520x; 1.0564x over previous
#include <cuda_runtime.h>
#include <cuda_bf16.h>
#include <math.h>
#include <stdint.h>

#define BB 16
#define SS 1024
#define DD 1024
#define CH 64
#define RR 1024           // CH*BB rows per chunk
#define NC 16             // SS/CH chunks
#define SB (SS*BB)        // 16384 rows total
#define ETA_F (0.01f*2.0f/(16.0f*1024.0f))

// ---------------- device scratch ----------------
__device__ float g_HT[SB*DD];
__device__ float g_STATE[SB*DD];
__device__ float g_PROBE[SB*DD];
__device__ float g_PBASE[SB*DD];   // PROBE@W0^T (all chunks)
__device__ float g_OT[SB*DD];
__device__ float g_X1[SB*DD];
__device__ float g_U[SB*DD];
__device__ float g_UW[DD*DD];      // accumulated A^T TV (fp32 master)
__device__ float g_P[RR*DD];       // per-chunk corrected P (fp32)
__device__ __nv_bfloat16 g_HTh[SB*DD];
__device__ __nv_bfloat16 g_TVh[SB*DD];
__device__ __nv_bfloat16 g_ABh[SB*DD];   // base A = TV@W0^T - STATE (bf16)
__device__ __nv_bfloat16 g_PRh[SB*DD];
__device__ __nv_bfloat16 g_H2h[SB*DD];
__device__ __nv_bfloat16 g_UWh[DD*DD];
__device__ __nv_bfloat16 g_Wsth[DD*DD];
__device__ __nv_bfloat16 g_W0h[DD*DD];
__device__ __nv_bfloat16 g_Wp1h[DD*DD];
__device__ __nv_bfloat16 g_Wp2h[DD*DD];
__device__ __nv_bfloat16 g_Ah[RR*DD];    // corrected A (bf16, row-major)
__device__ __nv_bfloat16 g_Ath[DD*RR];   // corrected A transposed
__device__ __nv_bfloat16 g_Hbh[(long)NC*RR*RR];

// ---------------- helpers ----------------
__device__ __forceinline__ float tf32r(float x) {
    unsigned u;
    asm("cvt.rna.tf32.f32 %0, %1;" : "=r"(u) : "f"(x));
    return __uint_as_float(u);
}
__device__ __forceinline__ uint32_t smem_u32(const void* p) {
    uint32_t a;
    asm("{ .reg .u64 t; cvta.to.shared.u64 t, %1; cvt.u32.u64 %0, t; }"
        : "=r"(a) : "l"(p));
    return a;
}
__device__ __forceinline__ void cpa16(uint32_t d, const void* g) {
    asm volatile("cp.async.cg.shared.global [%0], [%1], 16;" :: "r"(d), "l"(g));
}
__device__ __forceinline__ void cpa_commit() {
    asm volatile("cp.async.commit_group;" ::: "memory");
}
__device__ __forceinline__ void mma_tf32(float* c, const unsigned* a, const unsigned* b) {
    asm volatile(
        "mma.sync.aligned.m16n8k8.row.col.f32.tf32.tf32.f32 "
        "{%0,%1,%2,%3}, {%4,%5,%6,%7}, {%8,%9}, {%0,%1,%2,%3};\n"
        : "+f"(c[0]), "+f"(c[1]), "+f"(c[2]), "+f"(c[3])
        : "r"(a[0]), "r"(a[1]), "r"(a[2]), "r"(a[3]), "r"(b[0]), "r"(b[1]));
}
__device__ __forceinline__ void mma_bf16(float* c, const unsigned* a, const unsigned* b) {
    asm volatile(
        "mma.sync.aligned.m16n8k16.row.col.f32.bf16.bf16.f32 "
        "{%0,%1,%2,%3}, {%4,%5,%6,%7}, {%8,%9}, {%0,%1,%2,%3};\n"
        : "+f"(c[0]), "+f"(c[1]), "+f"(c[2]), "+f"(c[3])
        : "r"(a[0]), "r"(a[1]), "r"(a[2]), "r"(a[3]), "r"(b[0]), "r"(b[1]));
}
__device__ __forceinline__ void ldsm4(unsigned& r0, unsigned& r1, unsigned& r2,
                                      unsigned& r3, unsigned addr) {
    asm volatile("ldmatrix.sync.aligned.m8n8.x4.shared.b16 {%0,%1,%2,%3},[%4];"
                 : "=r"(r0), "=r"(r1), "=r"(r2), "=r"(r3) : "r"(addr));
}
__device__ __forceinline__ void ldsm4t(unsigned& r0, unsigned& r1, unsigned& r2,
                                       unsigned& r3, unsigned addr) {
    asm volatile("ldmatrix.sync.aligned.m8n8.x4.trans.shared.b16 {%0,%1,%2,%3},[%4];"
                 : "=r"(r0), "=r"(r1), "=r"(r2), "=r"(r3) : "r"(addr));
}

// ---------------- elementwise kernels ----------------
__global__ void k_cvt(const float* __restrict__ a, __nv_bfloat16* __restrict__ ah,
                      const float* __restrict__ b, __nv_bfloat16* __restrict__ bh) {
    long i = (long)blockIdx.x * blockDim.x + threadIdx.x;
    float4 v = *(const float4*)(a + i*4);
    *(__nv_bfloat162*)(ah + i*4)     = __floats2bfloat162_rn(v.x, v.y);
    *(__nv_bfloat162*)(ah + i*4 + 2) = __floats2bfloat162_rn(v.z, v.w);
    float4 w = *(const float4*)(b + i*4);
    *(__nv_bfloat162*)(bh + i*4)     = __floats2bfloat162_rn(w.x, w.y);
    *(__nv_bfloat162*)(bh + i*4 + 2) = __floats2bfloat162_rn(w.z, w.w);
}

__global__ void k_prep(const float* __restrict__ x, const float* __restrict__ a1,
                       float* __restrict__ HT, __nv_bfloat16* __restrict__ HTh) {
    long i4 = (long)blockIdx.x * blockDim.x + threadIdx.x;
    long flat = i4 * 4;
    int b = (int)(flat / ((long)SS*DD));
    int t = (int)((flat / DD) % SS);
    int d = (int)(flat % DD);
    float4 xv = *(const float4*)(x + flat);
    float4 av = *(const float4*)(a1 + d);
    float4 o;
    o.x = tanhf(av.x * xv.x); o.y = tanhf(av.y * xv.y);
    o.z = tanhf(av.z * xv.z); o.w = tanhf(av.w * xv.w);
    const long di = (long)(t*BB + b) * DD + d;
    *(float4*)(HT + di) = o;
    *(__nv_bfloat162*)(HTh + di)     = __floats2bfloat162_rn(o.x, o.y);
    *(__nv_bfloat162*)(HTh + di + 2) = __floats2bfloat162_rn(o.z, o.w);
}

__global__ void k_zero(float* __restrict__ a, __nv_bfloat16* __restrict__ ah) {
    long i = (long)blockIdx.x * blockDim.x + threadIdx.x;
    *(float4*)(a + i*4) = make_float4(0.f, 0.f, 0.f, 0.f);
    *(float2*)((float*)(ah + i*4)) = make_float2(0.f, 0.f);
}

__global__ void k_x1h2(const float* __restrict__ OT, const float* __restrict__ x,
                       const float* __restrict__ a2,
                       float* __restrict__ X1, __nv_bfloat16* __restrict__ H2h) {
    long i4 = (long)blockIdx.x * blockDim.x + threadIdx.x;
    long flat = i4 * 4;
    int b = (int)(flat / ((long)SS*DD));
    int t = (int)((flat / DD) % SS);
    int d = (int)(flat % DD);
    float4 ro = *(const float4*)(OT + ((long)(t*BB + b) * DD + d));
    float4 xv = *(const float4*)(x + flat);
    float4 av = *(const float4*)(a2 + d);
    float4 x1; x1.x = ro.x+xv.x; x1.y = ro.y+xv.y; x1.z = ro.z+xv.z; x1.w = ro.w+xv.w;
    *(float4*)(X1 + flat) = x1;
    float h0 = tanhf(av.x*x1.x), h1 = tanhf(av.y*x1.y);
    float h2 = tanhf(av.z*x1.z), h3 = tanhf(av.w*x1.w);
    *(__nv_bfloat162*)(H2h + flat)     = __floats2bfloat162_rn(h0, h1);
    *(__nv_bfloat162*)(H2h + flat + 2) = __floats2bfloat162_rn(h2, h3);
}

// ---------------- tf32 tensor-core GEMM (direct-precision paths) ----------
// MODE: 0 plain  7 plain + bf16 copy->P2
template<int BM,int BN,int MW,int NW,int MODE>
__global__ void __launch_bounds__(MW*NW*32, 2)
gemm_t(const float* __restrict__ A, int lda,
       const float* __restrict__ B, int ldb,
       float* __restrict__ C, int ldc, int K,
       const float* __restrict__ P1, const float* __restrict__ P2)
{
    constexpr int BK  = 16;
    constexpr int BKp = 20;
    constexpr int T   = MW*NW*32;
    constexpr int WM  = BM/MW, WN = BN/NW;
    constexpr int MT  = WM/16, NT = WN/8;
    constexpr int LPA = BM*BK/(4*T);
    constexpr int LPB = BN*BK/(4*T);

    const int m0 = blockIdx.y * BM, n0 = blockIdx.x * BN;

    __shared__ __align__(16) float As[2][BM][BKp];
    __shared__ __align__(16) float Bs[2][BN][BKp];

    const int tid  = threadIdx.x;
    const int lane = tid & 31;
    const int wid  = tid >> 5;
    const int wm   = wid / NW, wn = wid % NW;
    const int mw0  = wm * WM, nw0 = wn * WN;
    const int qr   = lane >> 2;
    const int qc   = lane & 3;
    const int lr   = lane & 7;
    const int aBase = (mw0 + lr + ((lane>>3)&1)*8) * BKp + ((lane>>4)&1)*4;
    const int bBase = (nw0 + lr + ((lane>>4)&1)*8) * BKp + ((lane>>3)&1)*4;

    float acc[MT][NT][4];
    #pragma unroll
    for (int i = 0; i < MT; ++i)
        #pragma unroll
        for (int j = 0; j < NT; ++j)
            #pragma unroll
            for (int q = 0; q < 4; ++q) acc[i][j][q] = 0.f;

    const int ktiles = K / BK;
    float4 pa[LPA], pb[LPB];

    auto gload = [&](int k0) {
        #pragma unroll
        for (int p = 0; p < LPA; ++p) {
            const int idx = tid + p*T;
            const int am = idx / (BK/4), akq = idx % (BK/4);
            pa[p] = *(const float4*)(A + (long)(m0 + am) * lda + k0 + 4*akq);
        }
        #pragma unroll
        for (int p = 0; p < LPB; ++p) {
            const int idx = tid + p*T;
            const int bn = idx / (BK/4), bkq = idx % (BK/4);
            pb[p] = *(const float4*)(B + (long)(n0 + bn) * ldb + k0 + 4*bkq);
        }
    };
    auto sstore = [&](int s) {
        #pragma unroll
        for (int p = 0; p < LPA; ++p) {
            const int idx = tid + p*T;
            const int am = idx / (BK/4), akq = idx % (BK/4);
            float4 w = make_float4(tf32r(pa[p].x), tf32r(pa[p].y),
                                   tf32r(pa[p].z), tf32r(pa[p].w));
            *(float4*)&As[s][am][4*akq] = w;
        }
        #pragma unroll
        for (int p = 0; p < LPB; ++p) {
            const int idx = tid + p*T;
            const int bn = idx / (BK/4), bkq = idx % (BK/4);
            float4 w = make_float4(tf32r(pb[p].x), tf32r(pb[p].y),
                                   tf32r(pb[p].z), tf32r(pb[p].w));
            *(float4*)&Bs[s][bn][4*bkq] = w;
        }
    };
    auto compute = [&](int s) {
        const unsigned sA = (unsigned)__cvta_generic_to_shared(&As[s][0][0]);
        const unsigned sB = (unsigned)__cvta_generic_to_shared(&Bs[s][0][0]);
        #pragma unroll
        for (int ks = 0; ks < BK; ks += 8) {
            unsigned af[MT][4];
            #pragma unroll
            for (int im = 0; im < MT; ++im)
                ldsm4(af[im][0], af[im][1], af[im][2], af[im][3],
                      sA + 4u*(aBase + im*16*BKp + ks));
            unsigned bf[NT][2];
            #pragma unroll
            for (int jp = 0; jp < NT/2; ++jp) {
                unsigned r0, r1, r2, r3;
                ldsm4(r0, r1, r2, r3, sB + 4u*(bBase + jp*16*BKp + ks));
                bf[2*jp][0] = r0; bf[2*jp][1] = r1;
                bf[2*jp+1][0] = r2; bf[2*jp+1][1] = r3;
            }
            #pragma unroll
            for (int im = 0; im < MT; ++im)
                #pragma unroll
                for (int jn = 0; jn < NT; ++jn)
                    mma_tf32(acc[im][jn], af[im], bf[jn]);
        }
    };

    gload(0);
    sstore(0);
    __syncthreads();

    for (int kt = 0; kt < ktiles; ++kt) {
        const bool more = (kt + 1 < ktiles);
        if (more) gload((kt+1)*BK);
        compute(kt & 1);
        if (more) sstore((kt+1) & 1);
        __syncthreads();
    }

    #pragma unroll
    for (int im = 0; im < MT; ++im) {
        #pragma unroll
        for (int jn = 0; jn < NT; ++jn) {
            #pragma unroll
            for (int h = 0; h < 2; ++h) {
                const int m = m0 + mw0 + im*16 + qr + h*8;
                const int n = n0 + nw0 + jn*8 + qc*2;
                const long ci = (long)m * ldc + n;
                float v0 = acc[im][jn][h*2 + 0];
                float v1 = acc[im][jn][h*2 + 1];
                if (MODE == 0) {
                    C[ci] = v0; C[ci+1] = v1;
                } else if (MODE == 7) {
                    C[ci] = v0; C[ci+1] = v1;
                    __nv_bfloat16* Cb = (__nv_bfloat16*)P2;
                    *(__nv_bfloat162*)(Cb + ci) = __floats2bfloat162_rn(v0, v1);
                }
            }
        }
    }
}

// ---------------- pipelined bf16 core (cp.async, 4 stages) ----------
// Tile (MW*32) x 64, MW*64 threads, warps (MW m) x (2 n), warp tile 32x32.
// OPA: 0 = A[M,K]; 2 = dual-source rows. OPB: 0 = B[N,K]; 1 = B[K,N].
// MODE: 2 tril mask -> bf16 Ch     3 C=P1a-ETA*acc (tril-K)
//       9 C+=acc & bf16->Ch        10 corr: A rows -> Ch/Ct bf16 (base=Bb),
//                                      P rows -> C fp32 (base=P1b)
//       11 Ch = bf16(acc - P1a)    12 C = acc (fp32)
//       15 C = gelu(acc) (fp32)    16 C = P1a*acc + P1b (fp32)
//       17 C = acc (fp32) & Ch = bf16(acc + noise[P1b b-major remap])
template<int MW,int OPA,int OPB,int MODE>
__device__ __forceinline__ void hcore(
    int m0, int n0,
    const __nv_bfloat16* A, const __nv_bfloat16* A2, long lda,
    const __nv_bfloat16* B, long ldb,
    float* C, __nv_bfloat16* Ch, __nv_bfloat16* Ct, long ldc, int K,
    const float* P1a, const float* P1b, const __nv_bfloat16* Bb, char* sm)
{
    constexpr int BM = MW*32, BK = 16;
    constexpr int ASTG = BM*48;
    constexpr int STG  = ASTG + 3072;
    const int tid = threadIdx.x, lane = tid & 31, wid = tid >> 5;
    const int wm = wid >> 1, wn = wid & 1;
    const int mw0 = wm * 32, nw0 = wn * 32;
    const int qr = lane >> 2, qc = lane & 3;
    const uint32_t sbase = smem_u32(sm);

    float acc[2][4][4];
    #pragma unroll
    for (int i = 0; i < 2; ++i)
        #pragma unroll
        for (int j = 0; j < 4; ++j)
            #pragma unroll
            for (int q = 0; q < 4; ++q) acc[i][j][q] = 0.f;

    int Kl = K;
    if (MODE == 3) { int t = m0 + BM; Kl = t < K ? t : K; }
    const int ktiles = Kl / BK;

    const int arow = tid >> 1, ahalf = tid & 1;    // blockDim == BM*2
    const int mg = m0 + arow;
    const __nv_bfloat16* Ar;
    if (OPA == 2) Ar = (mg < RR) ? (A + (long)mg * lda)
                                 : (A2 + (long)(mg - RR) * lda);
    else          Ar = A + (long)mg * lda;

    auto fill = [&](int kt) {
        if (kt < ktiles) {
            const long k0 = (long)kt * BK;
            const uint32_t as = sbase + (kt & 3) * STG;
            const uint32_t bs = as + ASTG;
            cpa16(as + arow*48 + ahalf*16, Ar + k0 + ahalf*8);
            if (MW == 2 || tid < 128) {
                if (OPB == 0) {
                    const int r = tid >> 1, h = tid & 1;
                    cpa16(bs + (r & 63)*48 + h*16, B + (long)(n0 + (r & 63))*ldb + k0 + h*8);
                } else {
                    const int kk = (tid >> 3) & 15, nc = tid & 7;
                    cpa16(bs + kk*144 + nc*16, B + (k0 + kk)*ldb + n0 + nc*8);
                }
            }
        }
        cpa_commit();
    };
    auto compute = [&](int kt) {
        const uint32_t sA = sbase + (kt & 3) * STG;
        const uint32_t sB = sA + ASTG;
        const int g = lane >> 3;
        unsigned af[2][4];
        #pragma unroll
        for (int im = 0; im < 2; ++im) {
            const int row = mw0 + im*16 + (g & 1)*8 + (lane & 7);
            const int kb = (g >> 1)*8;
            ldsm4(af[im][0], af[im][1], af[im][2], af[im][3],
                  sA + (unsigned)(row*48 + kb*2));
        }
        unsigned bf[4][2];
        #pragma unroll
        for (int jp = 0; jp < 2; ++jp) {
            unsigned r0, r1, r2, r3;
            if (OPB == 0) {
                const int row = nw0 + jp*16 + (g >> 1)*8 + (lane & 7);
                const int kb = (g & 1)*8;
                ldsm4(r0, r1, r2, r3, sB + (unsigned)(row*48 + kb*2));
            } else {
                const int krow = (g & 1)*8 + (lane & 7);
                const int col = nw0 + jp*16 + (g >> 1)*8;
                ldsm4t(r0, r1, r2, r3, sB + (unsigned)(krow*144 + col*2));
            }
            bf[2*jp][0] = r0; bf[2*jp][1] = r1;
            bf[2*jp+1][0] = r2; bf[2*jp+1][1] = r3;
        }
        #pragma unroll
        for (int im = 0; im < 2; ++im)
            #pragma unroll
            for (int jn = 0; jn < 4; ++jn)
                mma_bf16(acc[im][jn], af[im], bf[jn]);
    };

    fill(0); fill(1); fill(2);
    for (int kt = 0; kt < ktiles; ++kt) {
        asm volatile("cp.async.wait_group 2;" ::: "memory");
        __syncthreads();
        fill(kt + 3);
        compute(kt);
    }
    asm volatile("cp.async.wait_group 0;" ::: "memory");

    #pragma unroll
    for (int im = 0; im < 2; ++im) {
        #pragma unroll
        for (int jn = 0; jn < 4; ++jn) {
            #pragma unroll
            for (int h = 0; h < 2; ++h) {
                const int m = m0 + mw0 + im*16 + qr + h*8;
                const int n = n0 + nw0 + jn*8 + qc*2;
                const long ci = (long)m * ldc + n;
                float v0 = acc[im][jn][h*2 + 0];
                float v1 = acc[im][jn][h*2 + 1];
                if (MODE == 2) {
                    const bool z = ((n >> 4) > (m >> 4));
                    if (z) { v0 = 0.f; v1 = 0.f; }
                    *(__nv_bfloat162*)(Ch + ci) = __floats2bfloat162_rn(v0, v1);
                } else if (MODE == 3) {
                    float2 p = *(const float2*)(P1a + (long)m * ldc + n);
                    C[ci]   = p.x - ETA_F * v0;
                    C[ci+1] = p.y - ETA_F * v1;
                } else if (MODE == 9) {
                    float2 c = *(const float2*)(C + ci);
                    float w0 = c.x + v0, w1 = c.y + v1;
                    C[ci] = w0; C[ci+1] = w1;
                    *(__nv_bfloat162*)(Ch + ci) = __floats2bfloat162_rn(w0, w1);
                } else if (MODE == 10) {
                    if (m < RR) {
                        float b0 = __bfloat162float(Bb[(long)m * DD + n]);
                        float b1 = __bfloat162float(Bb[(long)m * DD + n + 1]);
                        float w0 = b0 - ETA_F * v0, w1 = b1 - ETA_F * v1;
                        *(__nv_bfloat162*)(Ch + (long)m * DD + n) =
                            __floats2bfloat162_rn(w0, w1);
                        Ct[(long)n * RR + m]       = __float2bfloat16(w0);
                        Ct[(long)(n + 1) * RR + m] = __float2bfloat16(w1);
                    } else {
                        const long pi = (long)(m - RR) * DD + n;
                        float2 p = *(const float2*)(P1b + pi);
                        C[pi]     = p.x - ETA_F * v0;
                        C[pi + 1] = p.y - ETA_F * v1;
                    }
                } else if (MODE == 11) {
                    float2 p = *(const float2*)(P1a + ci);
                    *(__nv_bfloat162*)(Ch + ci) =
                        __floats2bfloat162_rn(v0 - p.x, v1 - p.y);
                } else if (MODE == 12) {
                    C[ci] = v0; C[ci+1] = v1;
                } else if (MODE == 15) {
                    C[ci]   = 0.5f * v0 * (1.f + erff(v0 * 0.70710678118654752f));
                    C[ci+1] = 0.5f * v1 * (1.f + erff(v1 * 0.70710678118654752f));
                } else if (MODE == 16) {
                    float2 p = *(const float2*)(P1a + ci);
                    float2 q = *(const float2*)(P1b + ci);
                    C[ci]   = p.x * v0 + q.x;
                    C[ci+1] = p.y * v1 + q.y;
                } else if (MODE == 17) {
                    C[ci] = v0; C[ci+1] = v1;
                    const int tt = m >> 4, bb = m & 15;
                    const long ni = ((long)bb*SS + tt) * DD + n;
                    float2 nv = *(const float2*)(P1b + ni);
                    *(__nv_bfloat162*)(Ch + ci) =
                        __floats2bfloat162_rn(v0 + nv.x, v1 + nv.y);
                }
            }
        }
    }
}

// STATE = HTh @ Wsth^T (fp32 out) + fused TVh = bf16(STATE + noise)
__global__ void __launch_bounds__(256) k_bstate(
    const __nv_bfloat16* __restrict__ HTh, const __nv_bfloat16* __restrict__ Wsth,
    float* __restrict__ ST, const float* __restrict__ noise,
    __nv_bfloat16* __restrict__ TVh)
{
    __shared__ __align__(16) char sm[4*(128*48 + 3072)];
    hcore<4,0,0,17>(blockIdx.y * 128, blockIdx.x * 64, HTh, nullptr, DD,
                    Wsth, DD, ST, TVh, nullptr, DD, DD,
                    nullptr, noise, nullptr, sm);
}

// ABh = bf16(TVh @ W0h^T - ST)
__global__ void __launch_bounds__(256) k_babh(
    const __nv_bfloat16* __restrict__ TVh, const __nv_bfloat16* __restrict__ W0h,
    const float* __restrict__ ST, __nv_bfloat16* __restrict__ ABh)
{
    __shared__ __align__(16) char sm[4*(128*48 + 3072)];
    hcore<4,0,0,11>(blockIdx.y * 128, blockIdx.x * 64, TVh, nullptr, DD,
                    W0h, DD, nullptr, ABh, nullptr, DD, DD,
                    ST, nullptr, nullptr, sm);
}

// Hbh = bf16(trilblk(PRh @ TVh^T)), batched over chunks
__global__ void __launch_bounds__(256) k_gramh(
    const __nv_bfloat16* __restrict__ PRh, const __nv_bfloat16* __restrict__ TVh,
    __nv_bfloat16* __restrict__ Hbh)
{
    const int m0 = blockIdx.y * 128, n0 = blockIdx.x * 64;
    if (n0 >= m0 + 128) return;
    __shared__ __align__(16) char sm[4*(128*48 + 3072)];
    const long z = blockIdx.z;
    hcore<4,0,0,2>(m0, n0, PRh + z*RR*DD, nullptr, DD, TVh + z*RR*DD, DD,
                   nullptr, Hbh + z*RR*RR, nullptr, RR, DD,
                   nullptr, nullptr, nullptr, sm);
}

// U = gelu(H2h @ Wp1h^T) (fp32 out)
__global__ void __launch_bounds__(256) k_bgelu(
    const __nv_bfloat16* __restrict__ H2h, const __nv_bfloat16* __restrict__ Wp1h,
    float* __restrict__ U)
{
    __shared__ __align__(16) char sm[4*(128*48 + 3072)];
    hcore<4,0,0,15>(blockIdx.y * 128, blockIdx.x * 64, H2h, nullptr, DD,
                    Wp1h, DD, U, nullptr, nullptr, DD, DD,
                    nullptr, nullptr, nullptr, sm);
}

// out = U * (H2h @ Wp2h^T) + X1 (fp32 out)
__global__ void __launch_bounds__(256) k_bout(
    const __nv_bfloat16* __restrict__ H2h, const __nv_bfloat16* __restrict__ Wp2h,
    float* __restrict__ C, const float* __restrict__ U, const float* __restrict__ X1)
{
    __shared__ __align__(16) char sm[4*(128*48 + 3072)];
    hcore<4,0,0,16>(blockIdx.y * 128, blockIdx.x * 64, H2h, nullptr, DD,
                    Wp2h, DD, C, nullptr, nullptr, DD, DD,
                    U, X1, nullptr, sm);
}

// corr: A rows -> Ah/Ath bf16 (base ABh - ETA*TV@UW^T),
//       P rows -> Pbuf fp32 (base PB - ETA*PR@UW^T)
__global__ void __launch_bounds__(128) k_corr64(
    const __nv_bfloat16* __restrict__ TVhc, const __nv_bfloat16* __restrict__ PRhc,
    const __nv_bfloat16* __restrict__ UWh, float* __restrict__ Pbuf,
    __nv_bfloat16* __restrict__ Ah, __nv_bfloat16* __restrict__ Ath,
    const __nv_bfloat16* __restrict__ ABhc, const float* __restrict__ PBc)
{
    __shared__ __align__(16) char sm[4*(64*48 + 3072)];
    hcore<2,2,0,10>(blockIdx.y * 64, blockIdx.x * 64,
                    TVhc, PRhc, DD, UWh, DD,
                    Pbuf, Ah, Ath, DD, DD, nullptr, PBc, ABhc, sm);
}

// merged readout (y < RR/64) + UW update (y >= RR/64)
__global__ void __launch_bounds__(128) k_rduw64(
    const __nv_bfloat16* __restrict__ Hb, const __nv_bfloat16* __restrict__ Ah,
    float* __restrict__ OTc, const float* __restrict__ Pbuf,
    const __nv_bfloat16* __restrict__ Ath, const __nv_bfloat16* __restrict__ TVhc,
    float* __restrict__ UW, __nv_bfloat16* __restrict__ UWh)
{
    __shared__ __align__(16) char sm[4*(64*48 + 3072)];
    const int n0 = blockIdx.x * 64;
    if (blockIdx.y < RR/64) {
        // OT = P - ETA * trilHb @ A
        hcore<2,0,1,3>(blockIdx.y * 64, n0, Hb, nullptr, RR, Ah, DD,
                       OTc, nullptr, nullptr, DD, RR,
                       Pbuf, nullptr, nullptr, sm);
    } else {
        // UW += A^T @ TVc
        hcore<2,0,1,9>((blockIdx.y - RR/64) * 64, n0, Ath, nullptr, RR, TVhc, DD,
                       UW, UWh, nullptr, DD, RR,
                       nullptr, nullptr, nullptr, sm);
    }
}

// ---------------- host side ----------------
extern "C" void kernel_launch(void* const* d_in, const int* in_sizes, int n_in,
                              void* d_out, int out_size) {
    const float* x      = (const float*)d_in[0];
    const float* noise  = (const float*)d_in[1];
    const float* alpha1 = (const float*)d_in[2];
    const float* alpha2 = (const float*)d_in[3];
    const float* W_map  = (const float*)d_in[4];
    const float* W_st   = (const float*)d_in[5];
    const float* W_pr   = (const float*)d_in[6];
    const float* W_p1   = (const float*)d_in[7];
    const float* W_p2   = (const float*)d_in[8];
    float* out = (float*)d_out;

    float *HT, *ST, *PR, *PB, *OT, *X1, *U, *UW, *Pbuf;
    __nv_bfloat16 *HTh, *TVh, *ABh, *PRh, *H2h, *UWh, *Wsth, *W0h, *Wp1h, *Wp2h,
                  *Ah, *Ath, *Hbh;
    cudaGetSymbolAddress((void**)&HT, g_HT);
    cudaGetSymbolAddress((void**)&ST, g_STATE);
    cudaGetSymbolAddress((void**)&PR, g_PROBE);
    cudaGetSymbolAddress((void**)&PB, g_PBASE);
    cudaGetSymbolAddress((void**)&OT, g_OT);
    cudaGetSymbolAddress((void**)&X1, g_X1);
    cudaGetSymbolAddress((void**)&U,  g_U);
    cudaGetSymbolAddress((void**)&UW, g_UW);
    cudaGetSymbolAddress((void**)&Pbuf, g_P);
    cudaGetSymbolAddress((void**)&HTh, g_HTh);
    cudaGetSymbolAddress((void**)&TVh, g_TVh);
    cudaGetSymbolAddress((void**)&ABh, g_ABh);
    cudaGetSymbolAddress((void**)&PRh, g_PRh);
    cudaGetSymbolAddress((void**)&H2h, g_H2h);
    cudaGetSymbolAddress((void**)&UWh, g_UWh);
    cudaGetSymbolAddress((void**)&Wsth, g_Wsth);
    cudaGetSymbolAddress((void**)&W0h, g_W0h);
    cudaGetSymbolAddress((void**)&Wp1h, g_Wp1h);
    cudaGetSymbolAddress((void**)&Wp2h, g_Wp2h);
    cudaGetSymbolAddress((void**)&Ah,  g_Ah);
    cudaGetSymbolAddress((void**)&Ath, g_Ath);
    cudaGetSymbolAddress((void**)&Hbh, g_Hbh);

    const int EW_BLKS = (SB*DD/4) / 256;

    // 0: bf16 weight copies
    k_cvt<<<(DD*DD/4)/256, 256>>>(W_st, Wsth, W_map, W0h);
    k_cvt<<<(DD*DD/4)/256, 256>>>(W_p1, Wp1h, W_p2, Wp2h);
    // 1: h = tanh(alpha1*x), time-major (fp32 + bf16)
    k_prep<<<EW_BLKS, 256>>>(x, alpha1, HT, HTh);
    // 2: zero UW
    k_zero<<<(DD*DD/4)/256, 256>>>(UW, UWh);
    // 3: STATE = HTh@Wsth^T, fused TVh = bf16(STATE + noise)
    k_bstate<<<dim3(DD/64, SB/128), 256>>>(HTh, Wsth, ST, noise, TVh);
    // 4: ABh = bf16(TVh@W0h^T - STATE)
    k_babh<<<dim3(DD/64, SB/128), 256>>>(TVh, W0h, ST, ABh);
    // 5: PROBE = HT@Wpr^T (tf32, fp32 + bf16)  [direct path: stays tf32]
    gemm_t<128,128,2,4,7><<<dim3(DD/128, SB/128), 256>>>(
        HT, DD, W_pr, DD, PR, DD, DD, nullptr, (const float*)PRh);
    // 6: PBASE = PROBE@W0^T (tf32)  [direct path: stays tf32]
    gemm_t<128,128,2,4,0><<<dim3(DD/128, SB/128), 256>>>(
        PR, DD, W_map, DD, PB, DD, DD, nullptr, nullptr);
    // 7: cross-Gram -> Hbh (batched over 16 chunks of 1024)
    k_gramh<<<dim3(RR/64, RR/128, NC), 256>>>(PRh, TVh, Hbh);

    // chunk loop — 16 chunks of 1024 tim,  2 bf16 GEMM launches per chunk
    for (int c = 0; c < NC; ++c) {
        const __nv_bfloat16* TVhc = TVh + (long)c*RR*DD;
        const __nv_bfloat16* PRhc = PRh + (long)c*RR*DD;
        k_corr64<<<dim3(DD/64, (2*RR)/64), 128>>>(
            TVhc, PRhc, UWh, Pbuf, Ah, Ath,
            ABh + (long)c*RR*DD, PB + (long)c*RR*DD);
        k_rduw64<<<dim3(DD/64, 2*(RR/64)), 128>>>(
            Hbh + (long)c*RR*RR, Ah, OT + (long)c*RR*DD, Pbuf,
            Ath, TVhc, UW, UWh);
    }

    // x1 fp32 / h2 bf16
    k_x1h2<<<EW_BLKS, 256>>>(OT, x, alpha2, X1, H2h);
    // U = gelu(h2 @ Wp1^T)  (bf16 engine)
    k_bgelu<<<dim3(DD/64, SB/128), 256>>>(H2h, Wp1h, U);
    // out = U * (h2 @ Wp2^T) + X1  (bf16 engine)
    k_bout<<<dim3(DD/64, SB/128), 256>>>(H2h, Wp2h, out, U, X1);
}

// round 16
// speedup vs baseline: 1.4515x; 1.1594x over previous
#include <cuda_runtime.h>
#include <cuda_bf16.h>
#include <math.h>
#include <stdint.h>

#define BB 16
#define SS 1024
#define DD 1024
#define CH 64
#define RR 1024           // CH*BB rows per chunk
#define NC 16             // SS/CH chunks
#define SB (SS*BB)        // 16384 rows total
#define ETA_F (0.01f*2.0f/(16.0f*1024.0f))

// ---------------- device scratch ----------------
__device__ float g_HT[SB*DD];
__device__ float g_STATE[SB*DD];
__device__ float g_SCR[2*DD*DD];   // WprT, Wc
__device__ float g_PBASE[SB*DD];
__device__ float g_OT[SB*DD];
__device__ float g_X1[SB*DD];
__device__ float g_U[SB*DD];
__device__ float g_UW[DD*DD];      // accumulated AB^T TV (fp32 master)
__device__ float g_P[RR*DD];       // per-chunk corrected P (fp32)
__device__ __nv_bfloat16 g_HTh[SB*DD];
__device__ __nv_bfloat16 g_TVh[SB*DD];
__device__ __nv_bfloat16 g_ABh[SB*DD];    // base A = TV@W0^T - STATE (bf16)
__device__ __nv_bfloat16 g_ABth[SB*DD];   // per-chunk transposed AB [NC][DD][RR]
__device__ __nv_bfloat16 g_PRh[SB*DD];
__device__ __nv_bfloat16 g_H2h[SB*DD];
__device__ __nv_bfloat16 g_UWh[DD*DD];
__device__ __nv_bfloat16 g_Wsth[DD*DD];
__device__ __nv_bfloat16 g_W0h[DD*DD];
__device__ __nv_bfloat16 g_Wprh[DD*DD];
__device__ __nv_bfloat16 g_Wp1h[DD*DD];
__device__ __nv_bfloat16 g_Wp2h[DD*DD];
__device__ __nv_bfloat16 g_Hbh[(long)NC*RR*RR];

// ---------------- helpers ----------------
__device__ __forceinline__ float tf32r(float x) {
    unsigned u;
    asm("cvt.rna.tf32.f32 %0, %1;" : "=r"(u) : "f"(x));
    return __uint_as_float(u);
}
__device__ __forceinline__ uint32_t smem_u32(const void* p) {
    uint32_t a;
    asm("{ .reg .u64 t; cvta.to.shared.u64 t, %1; cvt.u32.u64 %0, t; }"
        : "=r"(a) : "l"(p));
    return a;
}
__device__ __forceinline__ void cpa16(uint32_t d, const void* g) {
    asm volatile("cp.async.cg.shared.global [%0], [%1], 16;" :: "r"(d), "l"(g));
}
__device__ __forceinline__ void cpa_commit() {
    asm volatile("cp.async.commit_group;" ::: "memory");
}
__device__ __forceinline__ void mma_tf32(float* c, const unsigned* a, const unsigned* b) {
    asm volatile(
        "mma.sync.aligned.m16n8k8.row.col.f32.tf32.tf32.f32 "
        "{%0,%1,%2,%3}, {%4,%5,%6,%7}, {%8,%9}, {%0,%1,%2,%3};\n"
        : "+f"(c[0]), "+f"(c[1]), "+f"(c[2]), "+f"(c[3])
        : "r"(a[0]), "r"(a[1]), "r"(a[2]), "r"(a[3]), "r"(b[0]), "r"(b[1]));
}
__device__ __forceinline__ void mma_bf16(float* c, const unsigned* a, const unsigned* b) {
    asm volatile(
        "mma.sync.aligned.m16n8k16.row.col.f32.bf16.bf16.f32 "
        "{%0,%1,%2,%3}, {%4,%5,%6,%7}, {%8,%9}, {%0,%1,%2,%3};\n"
        : "+f"(c[0]), "+f"(c[1]), "+f"(c[2]), "+f"(c[3])
        : "r"(a[0]), "r"(a[1]), "r"(a[2]), "r"(a[3]), "r"(b[0]), "r"(b[1]));
}
__device__ __forceinline__ void ldsm4(unsigned& r0, unsigned& r1, unsigned& r2,
                                      unsigned& r3, unsigned addr) {
    asm volatile("ldmatrix.sync.aligned.m8n8.x4.shared.b16 {%0,%1,%2,%3},[%4];"
                 : "=r"(r0), "=r"(r1), "=r"(r2), "=r"(r3) : "r"(addr));
}
__device__ __forceinline__ void ldsm4t(unsigned& r0, unsigned& r1, unsigned& r2,
                                       unsigned& r3, unsigned addr) {
    asm volatile("ldmatrix.sync.aligned.m8n8.x4.trans.shared.b16 {%0,%1,%2,%3},[%4];"
                 : "=r"(r0), "=r"(r1), "=r"(r2), "=r"(r3) : "r"(addr));
}

// ---------------- elementwise kernels ----------------
__global__ void k_cvt(const float* __restrict__ a, __nv_bfloat16* __restrict__ ah,
                      const float* __restrict__ b, __nv_bfloat16* __restrict__ bh) {
    long i = (long)blockIdx.x * blockDim.x + threadIdx.x;
    float4 v = *(const float4*)(a + i*4);
    *(__nv_bfloat162*)(ah + i*4)     = __floats2bfloat162_rn(v.x, v.y);
    *(__nv_bfloat162*)(ah + i*4 + 2) = __floats2bfloat162_rn(v.z, v.w);
    float4 w = *(const float4*)(b + i*4);
    *(__nv_bfloat162*)(bh + i*4)     = __floats2bfloat162_rn(w.x, w.y);
    *(__nv_bfloat162*)(bh + i*4 + 2) = __floats2bfloat162_rn(w.z, w.w);
}

__global__ void k_prep(const float* __restrict__ x, const float* __restrict__ a1,
                       float* __restrict__ HT, __nv_bfloat16* __restrict__ HTh) {
    long i4 = (long)blockIdx.x * blockDim.x + threadIdx.x;
    long flat = i4 * 4;
    int b = (int)(flat / ((long)SS*DD));
    int t = (int)((flat / DD) % SS);
    int d = (int)(flat % DD);
    float4 xv = *(const float4*)(x + flat);
    float4 av = *(const float4*)(a1 + d);
    float4 o;
    o.x = tanhf(av.x * xv.x); o.y = tanhf(av.y * xv.y);
    o.z = tanhf(av.z * xv.z); o.w = tanhf(av.w * xv.w);
    const long di = (long)(t*BB + b) * DD + d;
    *(float4*)(HT + di) = o;
    *(__nv_bfloat162*)(HTh + di)     = __floats2bfloat162_rn(o.x, o.y);
    *(__nv_bfloat162*)(HTh + di + 2) = __floats2bfloat162_rn(o.z, o.w);
}

__global__ void k_zero(float* __restrict__ a, __nv_bfloat16* __restrict__ ah) {
    long i = (long)blockIdx.x * blockDim.x + threadIdx.x;
    *(float4*)(a + i*4) = make_float4(0.f, 0.f, 0.f, 0.f);
    *(float2*)((float*)(ah + i*4)) = make_float2(0.f, 0.f);
}

// fp32 transpose DD x DD
__global__ void k_trw(const float* __restrict__ in, float* __restrict__ out) {
    __shared__ float t[32][33];
    const int x0 = blockIdx.x * 32, y0 = blockIdx.y * 32;
    const int x = threadIdx.x, y = threadIdx.y;
    #pragma unroll
    for (int i = 0; i < 32; i += 8)
        t[y+i][x] = in[(long)(y0 + y + i) * DD + x0 + x];
    __syncthreads();
    #pragma unroll
    for (int i = 0; i < 32; i += 8)
        out[(long)(x0 + y + i) * DD + y0 + x] = t[x][y+i];
}

__global__ void k_x1h2(const float* __restrict__ OT, const float* __restrict__ x,
                       const float* __restrict__ a2,
                       float* __restrict__ X1, __nv_bfloat16* __restrict__ H2h) {
    long i4 = (long)blockIdx.x * blockDim.x + threadIdx.x;
    long flat = i4 * 4;
    int b = (int)(flat / ((long)SS*DD));
    int t = (int)((flat / DD) % SS);
    int d = (int)(flat % DD);
    float4 ro = *(const float4*)(OT + ((long)(t*BB + b) * DD + d));
    float4 xv = *(const float4*)(x + flat);
    float4 av = *(const float4*)(a2 + d);
    float4 x1; x1.x = ro.x+xv.x; x1.y = ro.y+xv.y; x1.z = ro.z+xv.z; x1.w = ro.w+xv.w;
    *(float4*)(X1 + flat) = x1;
    float h0 = tanhf(av.x*x1.x), h1 = tanhf(av.y*x1.y);
    float h2 = tanhf(av.z*x1.z), h3 = tanhf(av.w*x1.w);
    *(__nv_bfloat162*)(H2h + flat)     = __floats2bfloat162_rn(h0, h1);
    *(__nv_bfloat162*)(H2h + flat + 2) = __floats2bfloat162_rn(h2, h3);
}

// ---------------- tf32 tensor-core GEMM (direct-precision path) ----------
template<int BM,int BN,int MW,int NW>
__global__ void __launch_bounds__(MW*NW*32, 2)
gemm_t(const float* __restrict__ A, int lda,
       const float* __restrict__ B, int ldb,
       float* __restrict__ C, int ldc, int K)
{
    constexpr int BK  = 16;
    constexpr int BKp = 20;
    constexpr int T   = MW*NW*32;
    constexpr int WM  = BM/MW, WN = BN/NW;
    constexpr int MT  = WM/16, NT = WN/8;
    constexpr int LPA = BM*BK/(4*T);
    constexpr int LPB = BN*BK/(4*T);

    const int m0 = blockIdx.y * BM, n0 = blockIdx.x * BN;

    __shared__ __align__(16) float As[2][BM][BKp];
    __shared__ __align__(16) float Bs[2][BN][BKp];

    const int tid  = threadIdx.x;
    const int lane = tid & 31;
    const int wid  = tid >> 5;
    const int wm   = wid / NW, wn = wid % NW;
    const int mw0  = wm * WM, nw0 = wn * WN;
    const int qr   = lane >> 2;
    const int qc   = lane & 3;
    const int lr   = lane & 7;
    const int aBase = (mw0 + lr + ((lane>>3)&1)*8) * BKp + ((lane>>4)&1)*4;
    const int bBase = (nw0 + lr + ((lane>>4)&1)*8) * BKp + ((lane>>3)&1)*4;

    float acc[MT][NT][4];
    #pragma unroll
    for (int i = 0; i < MT; ++i)
        #pragma unroll
        for (int j = 0; j < NT; ++j)
            #pragma unroll
            for (int q = 0; q < 4; ++q) acc[i][j][q] = 0.f;

    const int ktiles = K / BK;
    float4 pa[LPA], pb[LPB];

    auto gload = [&](int k0) {
        #pragma unroll
        for (int p = 0; p < LPA; ++p) {
            const int idx = tid + p*T;
            const int am = idx / (BK/4), akq = idx % (BK/4);
            pa[p] = *(const float4*)(A + (long)(m0 + am) * lda + k0 + 4*akq);
        }
        #pragma unroll
        for (int p = 0; p < LPB; ++p) {
            const int idx = tid + p*T;
            const int bn = idx / (BK/4), bkq = idx % (BK/4);
            pb[p] = *(const float4*)(B + (long)(n0 + bn) * ldb + k0 + 4*bkq);
        }
    };
    auto sstore = [&](int s) {
        #pragma unroll
        for (int p = 0; p < LPA; ++p) {
            const int idx = tid + p*T;
            const int am = idx / (BK/4), akq = idx % (BK/4);
            float4 w = make_float4(tf32r(pa[p].x), tf32r(pa[p].y),
                                   tf32r(pa[p].z), tf32r(pa[p].w));
            *(float4*)&As[s][am][4*akq] = w;
        }
        #pragma unroll
        for (int p = 0; p < LPB; ++p) {
            const int idx = tid + p*T;
            const int bn = idx / (BK/4), bkq = idx % (BK/4);
            float4 w = make_float4(tf32r(pb[p].x), tf32r(pb[p].y),
                                   tf32r(pb[p].z), tf32r(pb[p].w));
            *(float4*)&Bs[s][bn][4*bkq] = w;
        }
    };
    auto compute = [&](int s) {
        const unsigned sA = (unsigned)__cvta_generic_to_shared(&As[s][0][0]);
        const unsigned sB = (unsigned)__cvta_generic_to_shared(&Bs[s][0][0]);
        #pragma unroll
        for (int ks = 0; ks < BK; ks += 8) {
            unsigned af[MT][4];
            #pragma unroll
            for (int im = 0; im < MT; ++im)
                ldsm4(af[im][0], af[im][1], af[im][2], af[im][3],
                      sA + 4u*(aBase + im*16*BKp + ks));
            unsigned bf[NT][2];
            #pragma unroll
            for (int jp = 0; jp < NT/2; ++jp) {
                unsigned r0, r1, r2, r3;
                ldsm4(r0, r1, r2, r3, sB + 4u*(bBase + jp*16*BKp + ks));
                bf[2*jp][0] = r0; bf[2*jp][1] = r1;
                bf[2*jp+1][0] = r2; bf[2*jp+1][1] = r3;
            }
            #pragma unroll
            for (int im = 0; im < MT; ++im)
                #pragma unroll
                for (int jn = 0; jn < NT; ++jn)
                    mma_tf32(acc[im][jn], af[im], bf[jn]);
        }
    };

    gload(0);
    sstore(0);
    __syncthreads();

    for (int kt = 0; kt < ktiles; ++kt) {
        const bool more = (kt + 1 < ktiles);
        if (more) gload((kt+1)*BK);
        compute(kt & 1);
        if (more) sstore((kt+1) & 1);
        __syncthreads();
    }

    #pragma unroll
    for (int im = 0; im < MT; ++im) {
        #pragma unroll
        for (int jn = 0; jn < NT; ++jn) {
            #pragma unroll
            for (int h = 0; h < 2; ++h) {
                const int m = m0 + mw0 + im*16 + qr + h*8;
                const int n = n0 + nw0 + jn*8 + qc*2;
                const long ci = (long)m * ldc + n;
                C[ci]   = acc[im][jn][h*2 + 0];
                C[ci+1] = acc[im][jn][h*2 + 1];
            }
        }
    }
}

// ---------------- pipelined bf16 core (cp.async, 4 stages) ----------
// Tile (MW*32) x 64, MW*64 threads, warps (MW m) x (2 n), warp tile 32x32.
// OPB: 0 = B[N,K] (NT); 1 = B[K,N] (NN).
// MODE: 2 tril mask -> bf16 Ch   3 C=P1a-ETA*acc (tril-K)   8 C=P1a-ETA*acc (full K)
//       9 C+=acc & bf16->Ch      14 Ch=bf16(acc)            15 C=gelu(acc)
//       16 C=P1a*acc+P1b         17 C=acc & Ch=bf16(acc+noise[P1b])
//       18 Ch=bf16(acc-P1a) + chunk-transposed copy -> Ct
template<int MW,int OPB,int MODE>
__device__ __forceinline__ void hcore(
    int m0, int n0,
    const __nv_bfloat16* A, long lda,
    const __nv_bfloat16* B, long ldb,
    float* C, __nv_bfloat16* Ch, __nv_bfloat16* Ct, long ldc, int K,
    const float* P1a, const float* P1b, char* sm)
{
    constexpr int BM = MW*32, BK = 16;
    constexpr int ASTG = BM*48;
    constexpr int STG  = ASTG + 3072;
    const int tid = threadIdx.x, lane = tid & 31, wid = tid >> 5;
    const int wm = wid >> 1, wn = wid & 1;
    const int mw0 = wm * 32, nw0 = wn * 32;
    const int qr = lane >> 2, qc = lane & 3;
    const uint32_t sbase = smem_u32(sm);

    float acc[2][4][4];
    #pragma unroll
    for (int i = 0; i < 2; ++i)
        #pragma unroll
        for (int j = 0; j < 4; ++j)
            #pragma unroll
            for (int q = 0; q < 4; ++q) acc[i][j][q] = 0.f;

    int Kl = K;
    if (MODE == 3) { int t = m0 + BM; Kl = t < K ? t : K; }
    const int ktiles = Kl / BK;

    const int arow = tid >> 1, ahalf = tid & 1;    // blockDim == BM*2
    const __nv_bfloat16* Ar = A + (long)(m0 + arow) * lda;

    auto fill = [&](int kt) {
        if (kt < ktiles) {
            const long k0 = (long)kt * BK;
            const uint32_t as = sbase + (kt & 3) * STG;
            const uint32_t bs = as + ASTG;
            cpa16(as + arow*48 + ahalf*16, Ar + k0 + ahalf*8);
            if (MW == 2 || tid < 128) {
                if (OPB == 0) {
                    const int r = tid >> 1, h = tid & 1;
                    cpa16(bs + (r & 63)*48 + h*16, B + (long)(n0 + (r & 63))*ldb + k0 + h*8);
                } else {
                    const int kk = (tid >> 3) & 15, nc = tid & 7;
                    cpa16(bs + kk*144 + nc*16, B + (k0 + kk)*ldb + n0 + nc*8);
                }
            }
        }
        cpa_commit();
    };
    auto compute = [&](int kt) {
        const uint32_t sA = sbase + (kt & 3) * STG;
        const uint32_t sB = sA + ASTG;
        const int g = lane >> 3;
        unsigned af[2][4];
        #pragma unroll
        for (int im = 0; im < 2; ++im) {
            const int row = mw0 + im*16 + (g & 1)*8 + (lane & 7);
            const int kb = (g >> 1)*8;
            ldsm4(af[im][0], af[im][1], af[im][2], af[im][3],
                  sA + (unsigned)(row*48 + kb*2));
        }
        unsigned bf[4][2];
        #pragma unroll
        for (int jp = 0; jp < 2; ++jp) {
            unsigned r0, r1, r2, r3;
            if (OPB == 0) {
                const int row = nw0 + jp*16 + (g >> 1)*8 + (lane & 7);
                const int kb = (g & 1)*8;
                ldsm4(r0, r1, r2, r3, sB + (unsigned)(row*48 + kb*2));
            } else {
                const int krow = (g & 1)*8 + (lane & 7);
                const int col = nw0 + jp*16 + (g >> 1)*8;
                ldsm4t(r0, r1, r2, r3, sB + (unsigned)(krow*144 + col*2));
            }
            bf[2*jp][0] = r0; bf[2*jp][1] = r1;
            bf[2*jp+1][0] = r2; bf[2*jp+1][1] = r3;
        }
        #pragma unroll
        for (int im = 0; im < 2; ++im)
            #pragma unroll
            for (int jn = 0; jn < 4; ++jn)
                mma_bf16(acc[im][jn], af[im], bf[jn]);
    };

    fill(0); fill(1); fill(2);
    for (int kt = 0; kt < ktiles; ++kt) {
        asm volatile("cp.async.wait_group 2;" ::: "memory");
        __syncthreads();
        fill(kt + 3);
        compute(kt);
    }
    asm volatile("cp.async.wait_group 0;" ::: "memory");

    #pragma unroll
    for (int im = 0; im < 2; ++im) {
        #pragma unroll
        for (int jn = 0; jn < 4; ++jn) {
            #pragma unroll
            for (int h = 0; h < 2; ++h) {
                const int m = m0 + mw0 + im*16 + qr + h*8;
                const int n = n0 + nw0 + jn*8 + qc*2;
                const long ci = (long)m * ldc + n;
                float v0 = acc[im][jn][h*2 + 0];
                float v1 = acc[im][jn][h*2 + 1];
                if (MODE == 2) {
                    const bool z = ((n >> 4) > (m >> 4));
                    if (z) { v0 = 0.f; v1 = 0.f; }
                    *(__nv_bfloat162*)(Ch + ci) = __floats2bfloat162_rn(v0, v1);
                } else if (MODE == 3 || MODE == 8) {
                    float2 p = *(const float2*)(P1a + (long)m * ldc + n);
                    C[ci]   = p.x - ETA_F * v0;
                    C[ci+1] = p.y - ETA_F * v1;
                } else if (MODE == 9) {
                    float2 c = *(const float2*)(C + ci);
                    float w0 = c.x + v0, w1 = c.y + v1;
                    C[ci] = w0; C[ci+1] = w1;
                    *(__nv_bfloat162*)(Ch + ci) = __floats2bfloat162_rn(w0, w1);
                } else if (MODE == 14) {
                    *(__nv_bfloat162*)(Ch + ci) = __floats2bfloat162_rn(v0, v1);
                } else if (MODE == 15) {
                    C[ci]   = 0.5f * v0 * (1.f + erff(v0 * 0.70710678118654752f));
                    C[ci+1] = 0.5f * v1 * (1.f + erff(v1 * 0.70710678118654752f));
                } else if (MODE == 16) {
                    float2 p = *(const float2*)(P1a + ci);
                    float2 q = *(const float2*)(P1b + ci);
                    C[ci]   = p.x * v0 + q.x;
                    C[ci+1] = p.y * v1 + q.y;
                } else if (MODE == 17) {
                    C[ci] = v0; C[ci+1] = v1;
                    const int tt = m >> 4, bb = m & 15;
                    const long ni = ((long)bb*SS + tt) * DD + n;
                    float2 nv = *(const float2*)(P1b + ni);
                    *(__nv_bfloat162*)(Ch + ci) =
                        __floats2bfloat162_rn(v0 + nv.x, v1 + nv.y);
                } else if (MODE == 18) {
                    float2 p = *(const float2*)(P1a + ci);
                    float w0 = v0 - p.x, w1 = v1 - p.y;
                    *(__nv_bfloat162*)(Ch + ci) = __floats2bfloat162_rn(w0, w1);
                    const int cc = m >> 10;            // chunk (RR = 1024)
                    const int r  = m & (RR - 1);
                    __nv_bfloat16* Tt = Ct + (long)cc*DD*RR;
                    Tt[(long)n * RR + r]       = __float2bfloat16(w0);
                    Tt[(long)(n + 1) * RR + r] = __float2bfloat16(w1);
                }
            }
        }
    }
}

// STATE = HTh @ Wsth^T (fp32 out) + fused TVh = bf16(STATE + noise)
__global__ void __launch_bounds__(256) k_bstate(
    const __nv_bfloat16* __restrict__ HTh, const __nv_bfloat16* __restrict__ Wsth,
    float* __restrict__ ST, const float* __restrict__ noise,
    __nv_bfloat16* __restrict__ TVh)
{
    __shared__ __align__(16) char sm[4*(128*48 + 3072)];
    hcore<4,0,17>(blockIdx.y * 128, blockIdx.x * 64, HTh, DD,
                  Wsth, DD, ST, TVh, nullptr, DD, DD, nullptr, noise, sm);
}

// ABh = bf16(TVh @ W0h^T - ST) + chunk-transposed ABth
__global__ void __launch_bounds__(256) k_babh(
    const __nv_bfloat16* __restrict__ TVh, const __nv_bfloat16* __restrict__ W0h,
    const float* __restrict__ ST, __nv_bfloat16* __restrict__ ABh,
    __nv_bfloat16* __restrict__ ABth)
{
    __shared__ __align__(16) char sm[4*(128*48 + 3072)];
    hcore<4,0,18>(blockIdx.y * 128, blockIdx.x * 64, TVh, DD,
                  W0h, DD, nullptr, ABh, ABth, DD, DD, ST, nullptr, sm);
}

// PRh = bf16(HTh @ Wprh^T)
__global__ void __launch_bounds__(256) k_bprobe(
    const __nv_bfloat16* __restrict__ HTh, const __nv_bfloat16* __restrict__ Wprh,
    __nv_bfloat16* __restrict__ PRh)
{
    __shared__ __align__(16) char sm[4*(128*48 + 3072)];
    hcore<4,0,14>(blockIdx.y * 128, blockIdx.x * 64, HTh, DD,
                  Wprh, DD, nullptr, PRh, nullptr, DD, DD, nullptr, nullptr, sm);
}

// Hbh = bf16(trilblk(PRh @ TVh^T)), batched over chunks
__global__ void __launch_bounds__(256) k_gramh(
    const __nv_bfloat16* __restrict__ PRh, const __nv_bfloat16* __restrict__ TVh,
    __nv_bfloat16* __restrict__ Hbh)
{
    const int m0 = blockIdx.y * 128, n0 = blockIdx.x * 64;
    if (n0 >= m0 + 128) return;
    __shared__ __align__(16) char sm[4*(128*48 + 3072)];
    const long z = blockIdx.z;
    hcore<4,0,2>(m0, n0, PRh + z*RR*DD, DD, TVh + z*RR*DD, DD,
                 nullptr, Hbh + z*RR*RR, nullptr, RR, DD, nullptr, nullptr, sm);
}

// U = gelu(H2h @ Wp1h^T)
__global__ void __launch_bounds__(256) k_bgelu(
    const __nv_bfloat16* __restrict__ H2h, const __nv_bfloat16* __restrict__ Wp1h,
    float* __restrict__ U)
{
    __shared__ __align__(16) char sm[4*(128*48 + 3072)];
    hcore<4,0,15>(blockIdx.y * 128, blockIdx.x * 64, H2h, DD,
                  Wp1h, DD, U, nullptr, nullptr, DD, DD, nullptr, nullptr, sm);
}

// out = U * (H2h @ Wp2h^T) + X1
__global__ void __launch_bounds__(256) k_bout(
    const __nv_bfloat16* __restrict__ H2h, const __nv_bfloat16* __restrict__ Wp2h,
    float* __restrict__ C, const float* __restrict__ U, const float* __restrict__ X1)
{
    __shared__ __align__(16) char sm[4*(128*48 + 3072)];
    hcore<4,0,16>(blockIdx.y * 128, blockIdx.x * 64, H2h, DD,
                  Wp2h, DD, C, nullptr, nullptr, DD, DD, U, X1, sm);
}

// P correction only: Pbuf = PBc - ETA * PRhc @ UWh^T
__global__ void __launch_bounds__(128) k_pcorr(
    const __nv_bfloat16* __restrict__ PRhc, const __nv_bfloat16* __restrict__ UWh,
    float* __restrict__ Pbuf, const float* __restrict__ PBc)
{
    __shared__ __align__(16) char sm[4*(64*48 + 3072)];
    hcore<2,0,8>(blockIdx.y * 64, blockIdx.x * 64, PRhc, DD, UWh, DD,
                 Pbuf, nullptr, nullptr, DD, DD, PBc, nullptr, sm);
}

// merged readout (y < RR/64) + UW update (y >= RR/64), all from base AB
__global__ void __launch_bounds__(128) k_rduw64(
    const __nv_bfloat16* __restrict__ Hb, const __nv_bfloat16* __restrict__ ABhc,
    float* __restrict__ OTc, const float* __restrict__ Pbuf,
    const __nv_bfloat16* __restrict__ ABthc, const __nv_bfloat16* __restrict__ TVhc,
    float* __restrict__ UW, __nv_bfloat16* __restrict__ UWh)
{
    __shared__ __align__(16) char sm[4*(64*48 + 3072)];
    const int n0 = blockIdx.x * 64;
    if (blockIdx.y < RR/64) {
        // OT = P - ETA * trilHb @ AB
        hcore<2,1,3>(blockIdx.y * 64, n0, Hb, RR, ABhc, DD,
                     OTc, nullptr, nullptr, DD, RR, Pbuf, nullptr, sm);
    } else {
        // UW += AB^T @ TVc
        hcore<2,1,9>((blockIdx.y - RR/64) * 64, n0, ABthc, RR, TVhc, DD,
                     UW, UWh, nullptr, DD, RR, nullptr, nullptr, sm);
    }
}

// ---------------- host side ----------------
extern "C" void kernel_launch(void* const* d_in, const int* in_sizes, int n_in,
                              void* d_out, int out_size) {
    const float* x      = (const float*)d_in[0];
    const float* noise  = (const float*)d_in[1];
    const float* alpha1 = (const float*)d_in[2];
    const float* alpha2 = (const float*)d_in[3];
    const float* W_map  = (const float*)d_in[4];
    const float* W_st   = (const float*)d_in[5];
    const float* W_pr   = (const float*)d_in[6];
    const float* W_p1   = (const float*)d_in[7];
    const float* W_p2   = (const float*)d_in[8];
    float* out = (float*)d_out;

    float *HT, *ST, *SCR, *PB, *OT, *X1, *U, *UW, *Pbuf;
    __nv_bfloat16 *HTh, *TVh, *ABh, *ABth, *PRh, *H2h, *UWh;
    __nv_bfloat16 *Wsth, *W0h, *Wprh, *Wp1h, *Wp2h, *Hbh;
    cudaGetSymbolAddress((void**)&HT, g_HT);
    cudaGetSymbolAddress((void**)&ST, g_STATE);
    cudaGetSymbolAddress((void**)&SCR, g_SCR);
    cudaGetSymbolAddress((void**)&PB, g_PBASE);
    cudaGetSymbolAddress((void**)&OT, g_OT);
    cudaGetSymbolAddress((void**)&X1, g_X1);
    cudaGetSymbolAddress((void**)&U,  g_U);
    cudaGetSymbolAddress((void**)&UW, g_UW);
    cudaGetSymbolAddress((void**)&Pbuf, g_P);
    cudaGetSymbolAddress((void**)&HTh, g_HTh);
    cudaGetSymbolAddress((void**)&TVh, g_TVh);
    cudaGetSymbolAddress((void**)&ABh, g_ABh);
    cudaGetSymbolAddress((void**)&ABth, g_ABth);
    cudaGetSymbolAddress((void**)&PRh, g_PRh);
    cudaGetSymbolAddress((void**)&H2h, g_H2h);
    cudaGetSymbolAddress((void**)&UWh, g_UWh);
    cudaGetSymbolAddress((void**)&Wsth, g_Wsth);
    cudaGetSymbolAddress((void**)&W0h, g_W0h);
    cudaGetSymbolAddress((void**)&Wprh, g_Wprh);
    cudaGetSymbolAddress((void**)&Wp1h, g_Wp1h);
    cudaGetSymbolAddress((void**)&Wp2h, g_Wp2h);
    cudaGetSymbolAddress((void**)&Hbh, g_Hbh);

    float* WprT = SCR;
    float* Wc   = SCR + (long)DD*DD;
    const int EW_BLKS = (SB*DD/4) / 256;

    // 0: bf16 weight copies
    k_cvt<<<(DD*DD/4)/256, 256>>>(W_st, Wsth, W_map, W0h);
    k_cvt<<<(DD*DD/4)/256, 256>>>(W_p1, Wp1h, W_p2, Wp2h);
    k_cvt<<<(DD*DD/4)/256, 256>>>(W_pr, Wprh, W_pr, Wprh);
    // 1: h = tanh(alpha1*x), time-major (fp32 + bf16)
    k_prep<<<EW_BLKS, 256>>>(x, alpha1, HT, HTh);
    // 2: zero UW
    k_zero<<<(DD*DD/4)/256, 256>>>(UW, UWh);
    // 3: WprT = Wpr^T ; Wc = W0 @ Wpr (tf32)
    k_trw<<<dim3(32, 32), dim3(32, 8)>>>(W_pr, WprT);
    gemm_t<128,128,2,4><<<dim3(DD/128, DD/128), 256>>>(
        W_map, DD, WprT, DD, Wc, DD, DD);
    // 4: STATE = HTh@Wsth^T, fused TVh = bf16(STATE + noise)
    k_bstate<<<dim3(DD/64, SB/128), 256>>>(HTh, Wsth, ST, noise, TVh);
    // 5: ABh = bf16(TVh@W0h^T - STATE) + ABth
    k_babh<<<dim3(DD/64, SB/128), 256>>>(TVh, W0h, ST, ABh, ABth);
    // 6: PRh = bf16(HTh@Wprh^T)  (eta-path only)
    k_bprobe<<<dim3(DD/64, SB/128), 256>>>(HTh, Wprh, PRh);
    // 7: PBASE = HT@Wc^T (tf32, one big GEMM)  [direct path]
    gemm_t<128,128,2,4><<<dim3(DD/128, SB/128), 256>>>(
        HT, DD, Wc, DD, PB, DD, DD);
    // 8: cross-Gram -> Hbh (batched over 16 chunks of 1024)
    k_gramh<<<dim3(RR/64, RR/128, NC), 256>>>(PRh, TVh, Hbh);

    // chunk loop — P-correction + merged readout/UW
    for (int c = 0; c < NC; ++c) {
        const __nv_bfloat16* TVhc = TVh + (long)c*RR*DD;
        const __nv_bfloat16* PRhc = PRh + (long)c*RR*DD;
        const float* PBc = PB + (long)c*RR*DD;
        const float* Pp;
        if (c == 0) {
            Pp = PBc;
        } else {
            k_pcorr<<<dim3(DD/64, RR/64), 128>>>(PRhc, UWh, Pbuf, PBc);
            Pp = Pbuf;
        }
        k_rduw64<<<dim3(DD/64, 2*(RR/64)), 128>>>(
            Hbh + (long)c*RR*RR, ABh + (long)c*RR*DD, OT + (long)c*RR*DD, Pp,
            ABth + (long)c*DD*RR, TVhc, UW, UWh);
    }

    // x1 fp32 / h2 bf16
    k_x1h2<<<EW_BLKS, 256>>>(OT, x, alpha2, X1, H2h);
    // U = gelu(h2 @ Wp1^T)  (bf16 engine)
    k_bgelu<<<dim3(DD/64, SB/128), 256>>>(H2h, Wp1h, U);
    // out = U * (h2 @ Wp2^T) + X1  (bf16 engine)
    k_bout<<<dim3(DD/64, SB/128), 256>>>(H2h, Wp2h, out, U, X1);
}

// round 17
// speedup vs baseline: 1.6793x; 1.1569x over previous
#include <cuda_runtime.h>
#include <cuda_bf16.h>
#include <math.h>
#include <stdint.h>

#define BB 16
#define SS 1024
#define DD 1024
#define CH 64
#define RR 1024           // CH*BB rows per chunk
#define NC 16             // SS/CH chunks
#define SB (SS*BB)        // 16384 rows total
#define ETA_F (0.01f*2.0f/(16.0f*1024.0f))

// ---------------- device scratch ----------------
__device__ float g_HT[SB*DD];
__device__ float g_STATE[SB*DD];
__device__ float g_SCR[2*DD*DD];   // WprT, Wc
__device__ float g_PBASE[SB*DD];
__device__ float g_OT[SB*DD];
__device__ float g_X1[SB*DD];
__device__ float g_U[SB*DD];
__device__ __nv_bfloat16 g_HTh[SB*DD];
__device__ __nv_bfloat16 g_TVh[SB*DD];
__device__ __nv_bfloat16 g_ABh[SB*DD];    // base A = TV@W0^T - STATE (bf16)
__device__ __nv_bfloat16 g_ABth[SB*DD];   // per-chunk transposed AB [NC][DD][RR]
__device__ __nv_bfloat16 g_PRh[SB*DD];
__device__ __nv_bfloat16 g_H2h[SB*DD];
__device__ __nv_bfloat16 g_Wsth[DD*DD];
__device__ __nv_bfloat16 g_W0h[DD*DD];
__device__ __nv_bfloat16 g_Wprh[DD*DD];
__device__ __nv_bfloat16 g_Wp1h[DD*DD];
__device__ __nv_bfloat16 g_Wp2h[DD*DD];
__device__ __nv_bfloat16 g_Hbh[(long)NC*RR*RR];
__device__ __nv_bfloat16 g_INC[(long)NC*DD*DD];  // per-chunk AB^T TV
__device__ __nv_bfloat16 g_St[(long)NC*DD*DD];   // prefix sums

// ---------------- helpers ----------------
__device__ __forceinline__ float tf32r(float x) {
    unsigned u;
    asm("cvt.rna.tf32.f32 %0, %1;" : "=r"(u) : "f"(x));
    return __uint_as_float(u);
}
__device__ __forceinline__ uint32_t smem_u32(const void* p) {
    uint32_t a;
    asm("{ .reg .u64 t; cvta.to.shared.u64 t, %1; cvt.u32.u64 %0, t; }"
        : "=r"(a) : "l"(p));
    return a;
}
__device__ __forceinline__ void cpa16(uint32_t d, const void* g) {
    asm volatile("cp.async.cg.shared.global [%0], [%1], 16;" :: "r"(d), "l"(g));
}
__device__ __forceinline__ void cpa_commit() {
    asm volatile("cp.async.commit_group;" ::: "memory");
}
__device__ __forceinline__ void mma_tf32(float* c, const unsigned* a, const unsigned* b) {
    asm volatile(
        "mma.sync.aligned.m16n8k8.row.col.f32.tf32.tf32.f32 "
        "{%0,%1,%2,%3}, {%4,%5,%6,%7}, {%8,%9}, {%0,%1,%2,%3};\n"
        : "+f"(c[0]), "+f"(c[1]), "+f"(c[2]), "+f"(c[3])
        : "r"(a[0]), "r"(a[1]), "r"(a[2]), "r"(a[3]), "r"(b[0]), "r"(b[1]));
}
__device__ __forceinline__ void mma_bf16(float* c, const unsigned* a, const unsigned* b) {
    asm volatile(
        "mma.sync.aligned.m16n8k16.row.col.f32.bf16.bf16.f32 "
        "{%0,%1,%2,%3}, {%4,%5,%6,%7}, {%8,%9}, {%0,%1,%2,%3};\n"
        : "+f"(c[0]), "+f"(c[1]), "+f"(c[2]), "+f"(c[3])
        : "r"(a[0]), "r"(a[1]), "r"(a[2]), "r"(a[3]), "r"(b[0]), "r"(b[1]));
}
__device__ __forceinline__ void ldsm4(unsigned& r0, unsigned& r1, unsigned& r2,
                                      unsigned& r3, unsigned addr) {
    asm volatile("ldmatrix.sync.aligned.m8n8.x4.shared.b16 {%0,%1,%2,%3},[%4];"
                 : "=r"(r0), "=r"(r1), "=r"(r2), "=r"(r3) : "r"(addr));
}
__device__ __forceinline__ void ldsm4t(unsigned& r0, unsigned& r1, unsigned& r2,
                                       unsigned& r3, unsigned addr) {
    asm volatile("ldmatrix.sync.aligned.m8n8.x4.trans.shared.b16 {%0,%1,%2,%3},[%4];"
                 : "=r"(r0), "=r"(r1), "=r"(r2), "=r"(r3) : "r"(addr));
}

// ---------------- elementwise kernels ----------------
__global__ void k_cvt(const float* __restrict__ a, __nv_bfloat16* __restrict__ ah,
                      const float* __restrict__ b, __nv_bfloat16* __restrict__ bh) {
    long i = (long)blockIdx.x * blockDim.x + threadIdx.x;
    float4 v = *(const float4*)(a + i*4);
    *(__nv_bfloat162*)(ah + i*4)     = __floats2bfloat162_rn(v.x, v.y);
    *(__nv_bfloat162*)(ah + i*4 + 2) = __floats2bfloat162_rn(v.z, v.w);
    float4 w = *(const float4*)(b + i*4);
    *(__nv_bfloat162*)(bh + i*4)     = __floats2bfloat162_rn(w.x, w.y);
    *(__nv_bfloat162*)(bh + i*4 + 2) = __floats2bfloat162_rn(w.z, w.w);
}

__global__ void k_prep(const float* __restrict__ x, const float* __restrict__ a1,
                       float* __restrict__ HT, __nv_bfloat16* __restrict__ HTh) {
    long i4 = (long)blockIdx.x * blockDim.x + threadIdx.x;
    long flat = i4 * 4;
    int b = (int)(flat / ((long)SS*DD));
    int t = (int)((flat / DD) % SS);
    int d = (int)(flat % DD);
    float4 xv = *(const float4*)(x + flat);
    float4 av = *(const float4*)(a1 + d);
    float4 o;
    o.x = tanhf(av.x * xv.x); o.y = tanhf(av.y * xv.y);
    o.z = tanhf(av.z * xv.z); o.w = tanhf(av.w * xv.w);
    const long di = (long)(t*BB + b) * DD + d;
    *(float4*)(HT + di) = o;
    *(__nv_bfloat162*)(HTh + di)     = __floats2bfloat162_rn(o.x, o.y);
    *(__nv_bfloat162*)(HTh + di + 2) = __floats2bfloat162_rn(o.z, o.w);
}

// fp32 transpose DD x DD
__global__ void k_trw(const float* __restrict__ in, float* __restrict__ out) {
    __shared__ float t[32][33];
    const int x0 = blockIdx.x * 32, y0 = blockIdx.y * 32;
    const int x = threadIdx.x, y = threadIdx.y;
    #pragma unroll
    for (int i = 0; i < 32; i += 8)
        t[y+i][x] = in[(long)(y0 + y + i) * DD + x0 + x];
    __syncthreads();
    #pragma unroll
    for (int i = 0; i < 32; i += 8)
        out[(long)(x0 + y + i) * DD + y0 + x] = t[x][y+i];
}

// prefix scan over chunks: St[c] = sum_{j<=c} INC[j]  (fp32 accum)
__global__ void k_scan(const __nv_bfloat16* __restrict__ INC,
                       __nv_bfloat16* __restrict__ St) {
    const long idx = (long)blockIdx.x * blockDim.x + threadIdx.x;
    const long stride = (long)DD*DD/2;
    const __nv_bfloat162* ip = (const __nv_bfloat162*)INC + idx;
    __nv_bfloat162* op = (__nv_bfloat162*)St + idx;
    float sx = 0.f, sy = 0.f;
    #pragma unroll
    for (int c = 0; c < NC; ++c) {
        float2 v = __bfloat1622float2(ip[(long)c*stride]);
        sx += v.x; sy += v.y;
        op[(long)c*stride] = __floats2bfloat162_rn(sx, sy);
    }
}

__global__ void k_x1h2(const float* __restrict__ OT, const float* __restrict__ x,
                       const float* __restrict__ a2,
                       float* __restrict__ X1, __nv_bfloat16* __restrict__ H2h) {
    long i4 = (long)blockIdx.x * blockDim.x + threadIdx.x;
    long flat = i4 * 4;
    int b = (int)(flat / ((long)SS*DD));
    int t = (int)((flat / DD) % SS);
    int d = (int)(flat % DD);
    float4 ro = *(const float4*)(OT + ((long)(t*BB + b) * DD + d));
    float4 xv = *(const float4*)(x + flat);
    float4 av = *(const float4*)(a2 + d);
    float4 x1; x1.x = ro.x+xv.x; x1.y = ro.y+xv.y; x1.z = ro.z+xv.z; x1.w = ro.w+xv.w;
    *(float4*)(X1 + flat) = x1;
    float h0 = tanhf(av.x*x1.x), h1 = tanhf(av.y*x1.y);
    float h2 = tanhf(av.z*x1.z), h3 = tanhf(av.w*x1.w);
    *(__nv_bfloat162*)(H2h + flat)     = __floats2bfloat162_rn(h0, h1);
    *(__nv_bfloat162*)(H2h + flat + 2) = __floats2bfloat162_rn(h2, h3);
}

// ---------------- tf32 tensor-core GEMM (direct-precision path) ----------
template<int BM,int BN,int MW,int NW>
__global__ void __launch_bounds__(MW*NW*32, 2)
gemm_t(const float* __restrict__ A, int lda,
       const float* __restrict__ B, int ldb,
       float* __restrict__ C, int ldc, int K)
{
    constexpr int BK  = 16;
    constexpr int BKp = 20;
    constexpr int T   = MW*NW*32;
    constexpr int WM  = BM/MW, WN = BN/NW;
    constexpr int MT  = WM/16, NT = WN/8;
    constexpr int LPA = BM*BK/(4*T);
    constexpr int LPB = BN*BK/(4*T);

    const int m0 = blockIdx.y * BM, n0 = blockIdx.x * BN;

    __shared__ __align__(16) float As[2][BM][BKp];
    __shared__ __align__(16) float Bs[2][BN][BKp];

    const int tid  = threadIdx.x;
    const int lane = tid & 31;
    const int wid  = tid >> 5;
    const int wm   = wid / NW, wn = wid % NW;
    const int mw0  = wm * WM, nw0 = wn * WN;
    const int qr   = lane >> 2;
    const int qc   = lane & 3;
    const int lr   = lane & 7;
    const int aBase = (mw0 + lr + ((lane>>3)&1)*8) * BKp + ((lane>>4)&1)*4;
    const int bBase = (nw0 + lr + ((lane>>4)&1)*8) * BKp + ((lane>>3)&1)*4;

    float acc[MT][NT][4];
    #pragma unroll
    for (int i = 0; i < MT; ++i)
        #pragma unroll
        for (int j = 0; j < NT; ++j)
            #pragma unroll
            for (int q = 0; q < 4; ++q) acc[i][j][q] = 0.f;

    const int ktiles = K / BK;
    float4 pa[LPA], pb[LPB];

    auto gload = [&](int k0) {
        #pragma unroll
        for (int p = 0; p < LPA; ++p) {
            const int idx = tid + p*T;
            const int am = idx / (BK/4), akq = idx % (BK/4);
            pa[p] = *(const float4*)(A + (long)(m0 + am) * lda + k0 + 4*akq);
        }
        #pragma unroll
        for (int p = 0; p < LPB; ++p) {
            const int idx = tid + p*T;
            const int bn = idx / (BK/4), bkq = idx % (BK/4);
            pb[p] = *(const float4*)(B + (long)(n0 + bn) * ldb + k0 + 4*bkq);
        }
    };
    auto sstore = [&](int s) {
        #pragma unroll
        for (int p = 0; p < LPA; ++p) {
            const int idx = tid + p*T;
            const int am = idx / (BK/4), akq = idx % (BK/4);
            float4 w = make_float4(tf32r(pa[p].x), tf32r(pa[p].y),
                                   tf32r(pa[p].z), tf32r(pa[p].w));
            *(float4*)&As[s][am][4*akq] = w;
        }
        #pragma unroll
        for (int p = 0; p < LPB; ++p) {
            const int idx = tid + p*T;
            const int bn = idx / (BK/4), bkq = idx % (BK/4);
            float4 w = make_float4(tf32r(pb[p].x), tf32r(pb[p].y),
                                   tf32r(pb[p].z), tf32r(pb[p].w));
            *(float4*)&Bs[s][bn][4*bkq] = w;
        }
    };
    auto compute = [&](int s) {
        const unsigned sA = (unsigned)__cvta_generic_to_shared(&As[s][0][0]);
        const unsigned sB = (unsigned)__cvta_generic_to_shared(&Bs[s][0][0]);
        #pragma unroll
        for (int ks = 0; ks < BK; ks += 8) {
            unsigned af[MT][4];
            #pragma unroll
            for (int im = 0; im < MT; ++im)
                ldsm4(af[im][0], af[im][1], af[im][2], af[im][3],
                      sA + 4u*(aBase + im*16*BKp + ks));
            unsigned bf[NT][2];
            #pragma unroll
            for (int jp = 0; jp < NT/2; ++jp) {
                unsigned r0, r1, r2, r3;
                ldsm4(r0, r1, r2, r3, sB + 4u*(bBase + jp*16*BKp + ks));
                bf[2*jp][0] = r0; bf[2*jp][1] = r1;
                bf[2*jp+1][0] = r2; bf[2*jp+1][1] = r3;
            }
            #pragma unroll
            for (int im = 0; im < MT; ++im)
                #pragma unroll
                for (int jn = 0; jn < NT; ++jn)
                    mma_tf32(acc[im][jn], af[im], bf[jn]);
        }
    };

    gload(0);
    sstore(0);
    __syncthreads();

    for (int kt = 0; kt < ktiles; ++kt) {
        const bool more = (kt + 1 < ktiles);
        if (more) gload((kt+1)*BK);
        compute(kt & 1);
        if (more) sstore((kt+1) & 1);
        __syncthreads();
    }

    #pragma unroll
    for (int im = 0; im < MT; ++im) {
        #pragma unroll
        for (int jn = 0; jn < NT; ++jn) {
            #pragma unroll
            for (int h = 0; h < 2; ++h) {
                const int m = m0 + mw0 + im*16 + qr + h*8;
                const int n = n0 + nw0 + jn*8 + qc*2;
                const long ci = (long)m * ldc + n;
                C[ci]   = acc[im][jn][h*2 + 0];
                C[ci+1] = acc[im][jn][h*2 + 1];
            }
        }
    }
}

// ---------------- pipelined bf16 core (cp.async, 4 stages) ----------
// Tile (MW*32) x 64, MW*64 threads, warps (MW m) x (2 n), warp tile 32x32.
// OPB: 0 = B[N,K] (NT); 1 = B[K,N] (NN).
// MODE: 2 tril mask -> bf16 Ch   3 C=P1a-ETA*acc (tril-K)   4 C=C-ETA*acc
//       14 Ch=bf16(acc)          15 C=gelu(acc)             16 C=P1a*acc+P1b
//       17 C=acc & Ch=bf16(acc+noise[P1b])
//       18 Ch=bf16(acc-P1a) + chunk-transposed copy -> Ct
template<int MW,int OPB,int MODE>
__device__ __forceinline__ void hcore(
    int m0, int n0,
    const __nv_bfloat16* A, long lda,
    const __nv_bfloat16* B, long ldb,
    float* C, __nv_bfloat16* Ch, __nv_bfloat16* Ct, long ldc, int K,
    const float* P1a, const float* P1b, char* sm)
{
    constexpr int BM = MW*32, BK = 16;
    constexpr int ASTG = BM*48;
    constexpr int STG  = ASTG + 3072;
    const int tid = threadIdx.x, lane = tid & 31, wid = tid >> 5;
    const int wm = wid >> 1, wn = wid & 1;
    const int mw0 = wm * 32, nw0 = wn * 32;
    const int qr = lane >> 2, qc = lane & 3;
    const uint32_t sbase = smem_u32(sm);

    float acc[2][4][4];
    #pragma unroll
    for (int i = 0; i < 2; ++i)
        #pragma unroll
        for (int j = 0; j < 4; ++j)
            #pragma unroll
            for (int q = 0; q < 4; ++q) acc[i][j][q] = 0.f;

    int Kl = K;
    if (MODE == 3) { int t = m0 + BM; Kl = t < K ? t : K; }
    const int ktiles = Kl / BK;

    const int arow = tid >> 1, ahalf = tid & 1;    // blockDim == BM*2
    const __nv_bfloat16* Ar = A + (long)(m0 + arow) * lda;

    auto fill = [&](int kt) {
        if (kt < ktiles) {
            const long k0 = (long)kt * BK;
            const uint32_t as = sbase + (kt & 3) * STG;
            const uint32_t bs = as + ASTG;
            cpa16(as + arow*48 + ahalf*16, Ar + k0 + ahalf*8);
            if (MW == 2 || tid < 128) {
                if (OPB == 0) {
                    const int r = tid >> 1, h = tid & 1;
                    cpa16(bs + (r & 63)*48 + h*16, B + (long)(n0 + (r & 63))*ldb + k0 + h*8);
                } else {
                    const int kk = (tid >> 3) & 15, nc = tid & 7;
                    cpa16(bs + kk*144 + nc*16, B + (k0 + kk)*ldb + n0 + nc*8);
                }
            }
        }
        cpa_commit();
    };
    auto compute = [&](int kt) {
        const uint32_t sA = sbase + (kt & 3) * STG;
        const uint32_t sB = sA + ASTG;
        const int g = lane >> 3;
        unsigned af[2][4];
        #pragma unroll
        for (int im = 0; im < 2; ++im) {
            const int row = mw0 + im*16 + (g & 1)*8 + (lane & 7);
            const int kb = (g >> 1)*8;
            ldsm4(af[im][0], af[im][1], af[im][2], af[im][3],
                  sA + (unsigned)(row*48 + kb*2));
        }
        unsigned bf[4][2];
        #pragma unroll
        for (int jp = 0; jp < 2; ++jp) {
            unsigned r0, r1, r2, r3;
            if (OPB == 0) {
                const int row = nw0 + jp*16 + (g >> 1)*8 + (lane & 7);
                const int kb = (g & 1)*8;
                ldsm4(r0, r1, r2, r3, sB + (unsigned)(row*48 + kb*2));
            } else {
                const int krow = (g & 1)*8 + (lane & 7);
                const int col = nw0 + jp*16 + (g >> 1)*8;
                ldsm4t(r0, r1, r2, r3, sB + (unsigned)(krow*144 + col*2));
            }
            bf[2*jp][0] = r0; bf[2*jp][1] = r1;
            bf[2*jp+1][0] = r2; bf[2*jp+1][1] = r3;
        }
        #pragma unroll
        for (int im = 0; im < 2; ++im)
            #pragma unroll
            for (int jn = 0; jn < 4; ++jn)
                mma_bf16(acc[im][jn], af[im], bf[jn]);
    };

    fill(0); fill(1); fill(2);
    for (int kt = 0; kt < ktiles; ++kt) {
        asm volatile("cp.async.wait_group 2;" ::: "memory");
        __syncthreads();
        fill(kt + 3);
        compute(kt);
    }
    asm volatile("cp.async.wait_group 0;" ::: "memory");

    #pragma unroll
    for (int im = 0; im < 2; ++im) {
        #pragma unroll
        for (int jn = 0; jn < 4; ++jn) {
            #pragma unroll
            for (int h = 0; h < 2; ++h) {
                const int m = m0 + mw0 + im*16 + qr + h*8;
                const int n = n0 + nw0 + jn*8 + qc*2;
                const long ci = (long)m * ldc + n;
                float v0 = acc[im][jn][h*2 + 0];
                float v1 = acc[im][jn][h*2 + 1];
                if (MODE == 2) {
                    const bool z = ((n >> 4) > (m >> 4));
                    if (z) { v0 = 0.f; v1 = 0.f; }
                    *(__nv_bfloat162*)(Ch + ci) = __floats2bfloat162_rn(v0, v1);
                } else if (MODE == 3) {
                    float2 p = *(const float2*)(P1a + (long)m * ldc + n);
                    C[ci]   = p.x - ETA_F * v0;
                    C[ci+1] = p.y - ETA_F * v1;
                } else if (MODE == 4) {
                    float2 cc = *(const float2*)(C + ci);
                    C[ci]   = cc.x - ETA_F * v0;
                    C[ci+1] = cc.y - ETA_F * v1;
                } else if (MODE == 14) {
                    *(__nv_bfloat162*)(Ch + ci) = __floats2bfloat162_rn(v0, v1);
                } else if (MODE == 15) {
                    C[ci]   = 0.5f * v0 * (1.f + erff(v0 * 0.70710678118654752f));
                    C[ci+1] = 0.5f * v1 * (1.f + erff(v1 * 0.70710678118654752f));
                } else if (MODE == 16) {
                    float2 p = *(const float2*)(P1a + ci);
                    float2 q = *(const float2*)(P1b + ci);
                    C[ci]   = p.x * v0 + q.x;
                    C[ci+1] = p.y * v1 + q.y;
                } else if (MODE == 17) {
                    C[ci] = v0; C[ci+1] = v1;
                    const int tt = m >> 4, bb = m & 15;
                    const long ni = ((long)bb*SS + tt) * DD + n;
                    float2 nv = *(const float2*)(P1b + ni);
                    *(__nv_bfloat162*)(Ch + ci) =
                        __floats2bfloat162_rn(v0 + nv.x, v1 + nv.y);
                } else if (MODE == 18) {
                    float2 p = *(const float2*)(P1a + ci);
                    float w0 = v0 - p.x, w1 = v1 - p.y;
                    *(__nv_bfloat162*)(Ch + ci) = __floats2bfloat162_rn(w0, w1);
                    const int cc = m >> 10;            // chunk (RR = 1024)
                    const int r  = m & (RR - 1);
                    __nv_bfloat16* Tt = Ct + (long)cc*DD*RR;
                    Tt[(long)n * RR + r]       = __float2bfloat16(w0);
                    Tt[(long)(n + 1) * RR + r] = __float2bfloat16(w1);
                }
            }
        }
    }
}

// STATE = HTh @ Wsth^T (fp32 out) + fused TVh = bf16(STATE + noise)
__global__ void __launch_bounds__(256) k_bstate(
    const __nv_bfloat16* __restrict__ HTh, const __nv_bfloat16* __restrict__ Wsth,
    float* __restrict__ ST, const float* __restrict__ noise,
    __nv_bfloat16* __restrict__ TVh)
{
    __shared__ __align__(16) char sm[4*(128*48 + 3072)];
    hcore<4,0,17>(blockIdx.y * 128, blockIdx.x * 64, HTh, DD,
                  Wsth, DD, ST, TVh, nullptr, DD, DD, nullptr, noise, sm);
}

// ABh = bf16(TVh @ W0h^T - ST) + chunk-transposed ABth
__global__ void __launch_bounds__(256) k_babh(
    const __nv_bfloat16* __restrict__ TVh, const __nv_bfloat16* __restrict__ W0h,
    const float* __restrict__ ST, __nv_bfloat16* __restrict__ ABh,
    __nv_bfloat16* __restrict__ ABth)
{
    __shared__ __align__(16) char sm[4*(128*48 + 3072)];
    hcore<4,0,18>(blockIdx.y * 128, blockIdx.x * 64, TVh, DD,
                  W0h, DD, nullptr, ABh, ABth, DD, DD, ST, nullptr, sm);
}

// PRh = bf16(HTh @ Wprh^T)
__global__ void __launch_bounds__(256) k_bprobe(
    const __nv_bfloat16* __restrict__ HTh, const __nv_bfloat16* __restrict__ Wprh,
    __nv_bfloat16* __restrict__ PRh)
{
    __shared__ __align__(16) char sm[4*(128*48 + 3072)];
    hcore<4,0,14>(blockIdx.y * 128, blockIdx.x * 64, HTh, DD,
                  Wprh, DD, nullptr, PRh, nullptr, DD, DD, nullptr, nullptr, sm);
}

// Hbh = bf16(trilblk(PRh @ TVh^T)), batched over chunks
__global__ void __launch_bounds__(256) k_gramh(
    const __nv_bfloat16* __restrict__ PRh, const __nv_bfloat16* __restrict__ TVh,
    __nv_bfloat16* __restrict__ Hbh)
{
    const int m0 = blockIdx.y * 128, n0 = blockIdx.x * 64;
    if (n0 >= m0 + 128) return;
    __shared__ __align__(16) char sm[4*(128*48 + 3072)];
    const long z = blockIdx.z;
    hcore<4,0,2>(m0, n0, PRh + z*RR*DD, DD, TVh + z*RR*DD, DD,
                 nullptr, Hbh + z*RR*RR, nullptr, RR, DD, nullptr, nullptr, sm);
}

// INC_z = bf16(ABth_z @ TVh_z)  (batched, OPB=1)
__global__ void __launch_bounds__(256) k_inc(
    const __nv_bfloat16* __restrict__ ABth, const __nv_bfloat16* __restrict__ TVh,
    __nv_bfloat16* __restrict__ INC)
{
    __shared__ __align__(16) char sm[4*(128*48 + 3072)];
    const long z = blockIdx.z;
    hcore<4,1,14>(blockIdx.y * 128, blockIdx.x * 64,
                  ABth + z*DD*RR, RR, TVh + z*RR*DD, DD,
                  nullptr, INC + z*DD*DD, nullptr, DD, RR, nullptr, nullptr, sm);
}

// OT_z = PB_z - ETA * trilHb_z @ AB_z  (batched, OPB=1, tril-K)
__global__ void __launch_bounds__(256) k_rdtril(
    const __nv_bfloat16* __restrict__ Hbh, const __nv_bfloat16* __restrict__ ABh,
    const float* __restrict__ PB, float* __restrict__ OT)
{
    __shared__ __align__(16) char sm[4*(128*48 + 3072)];
    const long z = blockIdx.z;
    hcore<4,1,3>(blockIdx.y * 128, blockIdx.x * 64,
                 Hbh + z*RR*RR, RR, ABh + z*RR*DD, DD,
                 OT + z*RR*DD, nullptr, nullptr, DD, RR,
                 PB + z*RR*DD, nullptr, sm);
}

// OT_{z+1} -= ETA * PR_{z+1} @ St_z^T  (batched z=0..NC-2, OPB=0 NT)
__global__ void __launch_bounds__(256) k_term1(
    const __nv_bfloat16* __restrict__ PRh, const __nv_bfloat16* __restrict__ St,
    float* __restrict__ OT)
{
    __shared__ __align__(16) char sm[4*(128*48 + 3072)];
    const long z = blockIdx.z;                  // chunk c = z+1
    hcore<4,0,4>(blockIdx.y * 128, blockIdx.x * 64,
                 PRh + (z+1)*RR*DD, DD, St + z*DD*DD, DD,
                 OT + (z+1)*RR*DD, nullptr, nullptr, DD, DD,
                 nullptr, nullptr, sm);
}

// U = gelu(H2h @ Wp1h^T)
__global__ void __launch_bounds__(256) k_bgelu(
    const __nv_bfloat16* __restrict__ H2h, const __nv_bfloat16* __restrict__ Wp1h,
    float* __restrict__ U)
{
    __shared__ __align__(16) char sm[4*(128*48 + 3072)];
    hcore<4,0,15>(blockIdx.y * 128, blockIdx.x * 64, H2h, DD,
                  Wp1h, DD, U, nullptr, nullptr, DD, DD, nullptr, nullptr, sm);
}

// out = U * (H2h @ Wp2h^T) + X1
__global__ void __launch_bounds__(256) k_bout(
    const __nv_bfloat16* __restrict__ H2h, const __nv_bfloat16* __restrict__ Wp2h,
    float* __restrict__ C, const float* __restrict__ U, const float* __restrict__ X1)
{
    __shared__ __align__(16) char sm[4*(128*48 + 3072)];
    hcore<4,0,16>(blockIdx.y * 128, blockIdx.x * 64, H2h, DD,
                  Wp2h, DD, C, nullptr, nullptr, DD, DD, U, X1, sm);
}

// ---------------- host side ----------------
extern "C" void kernel_launch(void* const* d_in, const int* in_sizes, int n_in,
                              void* d_out, int out_size) {
    const float* x      = (const float*)d_in[0];
    const float* noise  = (const float*)d_in[1];
    const float* alpha1 = (const float*)d_in[2];
    const float* alpha2 = (const float*)d_in[3];
    const float* W_map  = (const float*)d_in[4];
    const float* W_st   = (const float*)d_in[5];
    const float* W_pr   = (const float*)d_in[6];
    const float* W_p1   = (const float*)d_in[7];
    const float* W_p2   = (const float*)d_in[8];
    float* out = (float*)d_out;

    float *HT, *ST, *SCR, *PB, *OT, *X1, *U;
    __nv_bfloat16 *HTh, *TVh, *ABh, *ABth, *PRh, *H2h;
    __nv_bfloat16 *Wsth, *W0h, *Wprh, *Wp1h, *Wp2h, *Hbh, *INC, *St;
    cudaGetSymbolAddress((void**)&HT, g_HT);
    cudaGetSymbolAddress((void**)&ST, g_STATE);
    cudaGetSymbolAddress((void**)&SCR, g_SCR);
    cudaGetSymbolAddress((void**)&PB, g_PBASE);
    cudaGetSymbolAddress((void**)&OT, g_OT);
    cudaGetSymbolAddress((void**)&X1, g_X1);
    cudaGetSymbolAddress((void**)&U,  g_U);
    cudaGetSymbolAddress((void**)&HTh, g_HTh);
    cudaGetSymbolAddress((void**)&TVh, g_TVh);
    cudaGetSymbolAddress((void**)&ABh, g_ABh);
    cudaGetSymbolAddress((void**)&ABth, g_ABth);
    cudaGetSymbolAddress((void**)&PRh, g_PRh);
    cudaGetSymbolAddress((void**)&H2h, g_H2h);
    cudaGetSymbolAddress((void**)&Wsth, g_Wsth);
    cudaGetSymbolAddress((void**)&W0h, g_W0h);
    cudaGetSymbolAddress((void**)&Wprh, g_Wprh);
    cudaGetSymbolAddress((void**)&Wp1h, g_Wp1h);
    cudaGetSymbolAddress((void**)&Wp2h, g_Wp2h);
    cudaGetSymbolAddress((void**)&Hbh, g_Hbh);
    cudaGetSymbolAddress((void**)&INC, g_INC);
    cudaGetSymbolAddress((void**)&St,  g_St);

    float* WprT = SCR;
    float* Wc   = SCR + (long)DD*DD;
    const int EW_BLKS = (SB*DD/4) / 256;

    // 0: bf16 weight copies
    k_cvt<<<(DD*DD/4)/256, 256>>>(W_st, Wsth, W_map, W0h);
    k_cvt<<<(DD*DD/4)/256, 256>>>(W_p1, Wp1h, W_p2, Wp2h);
    k_cvt<<<(DD*DD/4)/256, 256>>>(W_pr, Wprh, W_pr, Wprh);
    // 1: h = tanh(alpha1*x), time-major (fp32 + bf16)
    k_prep<<<EW_BLKS, 256>>>(x, alpha1, HT, HTh);
    // 2: WprT = Wpr^T ; Wc = W0 @ Wpr (tf32)
    k_trw<<<dim3(32, 32), dim3(32, 8)>>>(W_pr, WprT);
    gemm_t<128,128,2,4><<<dim3(DD/128, DD/128), 256>>>(
        W_map, DD, WprT, DD, Wc, DD, DD);
    // 3: STATE = HTh@Wsth^T, fused TVh = bf16(STATE + noise)
    k_bstate<<<dim3(DD/64, SB/128), 256>>>(HTh, Wsth, ST, noise, TVh);
    // 4: ABh = bf16(TVh@W0h^T - STATE) + ABth
    k_babh<<<dim3(DD/64, SB/128), 256>>>(TVh, W0h, ST, ABh, ABth);
    // 5: PRh = bf16(HTh@Wprh^T)  (eta-path only)
    k_bprobe<<<dim3(DD/64, SB/128), 256>>>(HTh, Wprh, PRh);
    // 6: PBASE = HT@Wc^T (tf32)  [direct path]
    gemm_t<128,128,2,4><<<dim3(DD/128, SB/128), 256>>>(
        HT, DD, Wc, DD, PB, DD, DD);
    // 7: cross-Gram -> Hbh (batched)
    k_gramh<<<dim3(RR/64, RR/128, NC), 256>>>(PRh, TVh, Hbh);
    // 8: INC_c = ABth_c @ TVh_c (batched)
    k_inc<<<dim3(DD/64, DD/128, NC), 256>>>(ABth, TVh, INC);
    // 9: prefix scan over chunks
    k_scan<<<(DD*DD/2)/256, 256>>>(INC, St);
    // 10: OT = PB - ETA*trilHb@AB (batched)
    k_rdtril<<<dim3(DD/64, RR/128, NC), 256>>>(Hbh, ABh, PB, OT);
    // 11: OT_c -= ETA*PR_c@St_{c-1}^T (batched, c>=1)
    k_term1<<<dim3(DD/64, RR/128, NC-1), 256>>>(PRh, St, OT);
    // 12: x1 fp32 / h2 bf16
    k_x1h2<<<EW_BLKS, 256>>>(OT, x, alpha2, X1, H2h);
    // 13: U = gelu(h2 @ Wp1^T)
    k_bgelu<<<dim3(DD/64, SB/128), 256>>>(H2h, Wp1h, U);
    // 14: out = U * (h2 @ Wp2^T) + X1
    k_bout<<<dim3(DD/64, SB/128), 256>>>(H2h, Wp2h, out, U, X1);
}